// round 4
// baseline (speedup 1.0000x reference)
#include <cuda_runtime.h>
#include <cuda_fp16.h>

#define N_NODES 50000
#define N_EDGES 600000
#define HID 128
#define NODE_DIM 64
#define EDGE_DIM 16
#define NLAYERS 3
#define NGRAPHS 256
#define BN_EPS 1e-5f

typedef unsigned long long u64;

// ---------------- scratch (device globals; no allocations allowed) ----------
__device__ float g_h[N_NODES * HID];        // node features (post-activation)
__device__ float g_zin[N_NODES * HID];      // h + agg (MLP input)
__device__ float g_z[N_NODES * HID];        // pre-BN MLP output
__device__ __half g_ea_h[N_EDGES * HID];    // encoded edge features, fp16, CSR order
__device__ float g_stats[2 * HID];          // column sums / sumsq
__device__ float g_pool[NGRAPHS * HID];     // pooled graph features
// CSR by destination
__device__ int g_cnt[N_NODES];
__device__ int g_off[N_NODES + 1];
__device__ int g_cur[N_NODES];
__device__ int g_csr_src[N_EDGES];
__device__ int g_slot[N_EDGES];             // edge e -> CSR slot

// ---------------- f32x2 packed helpers ---------------------------------------
__device__ __forceinline__ u64 pk2(float x, float y) {
    u64 r; asm("mov.b64 %0,{%1,%2};" : "=l"(r) : "f"(x), "f"(y)); return r;
}
__device__ __forceinline__ void upk2(u64 v, float& x, float& y) {
    asm("mov.b64 {%0,%1},%2;" : "=f"(x), "=f"(y) : "l"(v));
}
__device__ __forceinline__ u64 fma2(u64 a, u64 b, u64 c) {
    u64 d; asm("fma.rn.f32x2 %0,%1,%2,%3;" : "=l"(d) : "l"(a), "l"(b), "l"(c)); return d;
}

__device__ __forceinline__ void red_add_v4(float* p, float4 v) {
    asm volatile("red.global.add.v4.f32 [%0], {%1,%2,%3,%4};"
                 :: "l"(p), "f"(v.x), "f"(v.y), "f"(v.z), "f"(v.w) : "memory");
}

// ---------------- small zero kernels ----------------------------------------
__global__ void zero_cnt_kernel() {
    int i = blockIdx.x * blockDim.x + threadIdx.x;
    if (i < N_NODES) g_cnt[i] = 0;
}
__global__ void zero_stats_kernel() {
    int i = threadIdx.x;
    if (i < 2 * HID) g_stats[i] = 0.f;
}
__global__ void zero_pool_kernel() {
    int i = blockIdx.x * blockDim.x + threadIdx.x;
    if (i < NGRAPHS * HID) g_pool[i] = 0.f;
}

// ---------------- CSR build --------------------------------------------------
__global__ void csr_count_kernel(const int* __restrict__ eidx) {
    int e = blockIdx.x * blockDim.x + threadIdx.x;
    if (e < N_EDGES) atomicAdd(&g_cnt[eidx[N_EDGES + e]], 1);
}

__global__ void csr_scan_kernel() {  // single block, 1024 threads
    __shared__ int ssum[1024];
    int t = threadIdx.x;
    const int CH = (N_NODES + 1023) / 1024;
    int beg = t * CH;
    int end = min(beg + CH, N_NODES);
    int s = 0;
    for (int i = beg; i < end; i++) s += g_cnt[i];
    ssum[t] = s;
    __syncthreads();
    for (int off = 1; off < 1024; off <<= 1) {
        int v = (t >= off) ? ssum[t - off] : 0;
        __syncthreads();
        ssum[t] += v;
        __syncthreads();
    }
    int run = (t == 0) ? 0 : ssum[t - 1];
    for (int i = beg; i < end; i++) {
        g_off[i] = run;
        g_cur[i] = run;
        run += g_cnt[i];
    }
    if (t == 1023) g_off[N_NODES] = ssum[1023];
}

__global__ void csr_fill_kernel(const int* __restrict__ eidx) {
    int e = blockIdx.x * blockDim.x + threadIdx.x;
    if (e >= N_EDGES) return;
    int dst = eidx[N_EDGES + e];
    int slot = atomicAdd(&g_cur[dst], 1);
    g_csr_src[slot] = eidx[e];
    g_slot[e] = slot;
}

// ---------------- node encoder: h = x @ node_w + node_b ---------------------
__global__ void encoder_kernel(const float* __restrict__ x,
                               const float* __restrict__ W,
                               const float* __restrict__ b) {
    __shared__ float sW[NODE_DIM * HID];
    for (int i = threadIdx.x; i < NODE_DIM * HID; i += blockDim.x) sW[i] = W[i];
    __syncthreads();
    int lane = threadIdx.x & 31;
    int warp = (blockIdx.x * blockDim.x + threadIdx.x) >> 5;
    int nw = (gridDim.x * blockDim.x) >> 5;
    float4 bb = reinterpret_cast<const float4*>(b)[lane];
    for (int n = warp; n < N_NODES; n += nw) {
        const float4* xr = reinterpret_cast<const float4*>(x + (size_t)n * NODE_DIM);
        float4 acc = bb;
        #pragma unroll
        for (int kk = 0; kk < NODE_DIM / 4; kk++) {
            float4 xv = xr[kk];
            float xa[4] = {xv.x, xv.y, xv.z, xv.w};
            #pragma unroll
            for (int j = 0; j < 4; j++) {
                float4 w = *reinterpret_cast<const float4*>(&sW[(4 * kk + j) * HID + 4 * lane]);
                acc.x += xa[j] * w.x;
                acc.y += xa[j] * w.y;
                acc.z += xa[j] * w.z;
                acc.w += xa[j] * w.w;
            }
        }
        reinterpret_cast<float4*>(g_h + (size_t)n * HID)[lane] = acc;
    }
}

// ---- edge encoder (ONCE): ea = edge_attr @ edge_w + edge_b -> fp16, CSR order
__global__ void edge_encoder_kernel(const float* __restrict__ eattr,
                                    const float* __restrict__ W,
                                    const float* __restrict__ b) {
    __shared__ float sW[EDGE_DIM * HID];
    __shared__ float sb[HID];
    for (int i = threadIdx.x; i < EDGE_DIM * HID; i += blockDim.x) sW[i] = W[i];
    if (threadIdx.x < HID) sb[threadIdx.x] = b[threadIdx.x];
    __syncthreads();
    int lane = threadIdx.x & 31;
    int warp = (blockIdx.x * blockDim.x + threadIdx.x) >> 5;
    int nw = (gridDim.x * blockDim.x) >> 5;
    float4 bb = reinterpret_cast<const float4*>(sb)[lane];
    for (int e = warp; e < N_EDGES; e += nw) {
        const float4* ar = reinterpret_cast<const float4*>(eattr + (size_t)e * EDGE_DIM);
        float4 acc = bb;
        #pragma unroll
        for (int kk = 0; kk < EDGE_DIM / 4; kk++) {
            float4 av = ar[kk];
            float xa[4] = {av.x, av.y, av.z, av.w};
            #pragma unroll
            for (int j = 0; j < 4; j++) {
                float4 w = *reinterpret_cast<const float4*>(&sW[(4 * kk + j) * HID + 4 * lane]);
                acc.x += xa[j] * w.x;
                acc.y += xa[j] * w.y;
                acc.z += xa[j] * w.z;
                acc.w += xa[j] * w.w;
            }
        }
        int slot = __ldg(&g_slot[e]);
        union { __half2 h[2]; uint2 u; } cv;
        cv.h[0] = __floats2half2_rn(acc.x, acc.y);
        cv.h[1] = __floats2half2_rn(acc.z, acc.w);
        *reinterpret_cast<uint2*>(g_ea_h + (size_t)slot * HID + 4 * lane) = cv.u;
    }
}

// ---------------- aggregation: zin[n] = h[n] + sum_{e->n} relu(h[src]+ea[e])
__global__ void agg_kernel() {
    int lane = threadIdx.x & 31;
    int warp = (blockIdx.x * blockDim.x + threadIdx.x) >> 5;
    int nw = (gridDim.x * blockDim.x) >> 5;
    for (int n = warp; n < N_NODES; n += nw) {
        float4 acc = reinterpret_cast<const float4*>(g_h + (size_t)n * HID)[lane];
        int s = __ldg(&g_off[n]);
        int e = __ldg(&g_off[n + 1]);
        for (int idx = s; idx < e; idx++) {
            int src = __ldg(&g_csr_src[idx]);
            float4 hv = reinterpret_cast<const float4*>(g_h + (size_t)src * HID)[lane];
            uint2 u = *reinterpret_cast<const uint2*>(g_ea_h + (size_t)idx * HID + 4 * lane);
            __half2 h0 = *reinterpret_cast<__half2*>(&u.x);
            __half2 h1 = *reinterpret_cast<__half2*>(&u.y);
            float2 e0 = __half22float2(h0);
            float2 e1 = __half22float2(h1);
            acc.x += fmaxf(hv.x + e0.x, 0.f);
            acc.y += fmaxf(hv.y + e0.y, 0.f);
            acc.z += fmaxf(hv.z + e1.x, 0.f);
            acc.w += fmaxf(hv.w + e1.y, 0.f);
        }
        reinterpret_cast<float4*>(g_zin + (size_t)n * HID)[lane] = acc;
    }
}

// ---------------- per-layer MLP: z = relu(zin@W1+b1)@W2+b2, + BN stats ------
// dyn smem (floats): W1[16384] W2[16384] InT[16384] B1[128] B2[128]
#define TROWS 128
#define MLP_THREADS 512
#define MLP_SMEM_FLOATS (2 * HID * HID + TROWS * HID + 2 * HID)
__global__ __launch_bounds__(MLP_THREADS, 1)
void mlp_kernel(const float* __restrict__ W1, const float* __restrict__ B1,
                const float* __restrict__ W2, const float* __restrict__ B2) {
    extern __shared__ float sm[];
    float* sW1 = sm;
    float* sW2 = sm + HID * HID;
    float* sIn = sm + 2 * HID * HID;          // 128x128, reused for T
    float* sB1 = sIn + TROWS * HID;
    float* sB2 = sB1 + HID;

    int tid = threadIdx.x;
    for (int i = tid; i < HID * HID; i += MLP_THREADS) { sW1[i] = W1[i]; sW2[i] = W2[i]; }
    if (tid < HID) { sB1[tid] = B1[tid]; sB2[tid] = B2[tid]; }
    __syncthreads();

    int c0 = (tid & 15) * 8;      // 8 output columns per thread
    int r0 = (tid >> 4) * 4;      // 4 rows per thread

    u64 bb1[4], bb2[4];
    #pragma unroll
    for (int j = 0; j < 4; j++) {
        bb1[j] = pk2(sB1[c0 + 2 * j], sB1[c0 + 2 * j + 1]);
        bb2[j] = pk2(sB2[c0 + 2 * j], sB2[c0 + 2 * j + 1]);
    }

    int rpb = (N_NODES + gridDim.x - 1) / gridDim.x;
    int base = blockIdx.x * rpb;
    int rend = min(base + rpb, N_NODES);

    float ls[8], lss[8];
    #pragma unroll
    for (int j = 0; j < 8; j++) { ls[j] = 0.f; lss[j] = 0.f; }

    for (int rbase = base; rbase < rend; rbase += TROWS) {
        // load input tile (128 rows x 128 cols)
        for (int i = tid; i < TROWS * HID / 4; i += MLP_THREADS) {
            int r = i >> 5;
            int q = i & 31;
            int row = rbase + r;
            float4 v = make_float4(0.f, 0.f, 0.f, 0.f);
            if (row < rend) v = reinterpret_cast<const float4*>(g_zin + (size_t)row * HID)[q];
            reinterpret_cast<float4*>(sIn)[i] = v;
        }
        __syncthreads();

        // stage 1: T = relu(In @ W1 + b1), accumulate in f32x2 pairs
        u64 acc[4][4];
        #pragma unroll
        for (int i = 0; i < 4; i++)
            #pragma unroll
            for (int j = 0; j < 4; j++) acc[i][j] = bb1[j];
        #pragma unroll 2
        for (int k = 0; k < HID; k++) {
            const u64* wp = reinterpret_cast<const u64*>(&sW1[k * HID + c0]);
            u64 w0 = wp[0], w1 = wp[1], w2 = wp[2], w3 = wp[3];
            #pragma unroll
            for (int i = 0; i < 4; i++) {
                float a = sIn[(r0 + i) * HID + k];
                u64 a2 = pk2(a, a);
                acc[i][0] = fma2(a2, w0, acc[i][0]);
                acc[i][1] = fma2(a2, w1, acc[i][1]);
                acc[i][2] = fma2(a2, w2, acc[i][2]);
                acc[i][3] = fma2(a2, w3, acc[i][3]);
            }
        }
        float t[4][8];
        #pragma unroll
        for (int i = 0; i < 4; i++)
            #pragma unroll
            for (int j = 0; j < 4; j++) {
                float v0, v1;
                upk2(acc[i][j], v0, v1);
                t[i][2 * j] = fmaxf(v0, 0.f);
                t[i][2 * j + 1] = fmaxf(v1, 0.f);
            }
        __syncthreads();   // everyone done reading In
        #pragma unroll
        for (int i = 0; i < 4; i++) {
            *reinterpret_cast<float4*>(&sIn[(r0 + i) * HID + c0]) =
                make_float4(t[i][0], t[i][1], t[i][2], t[i][3]);
            *reinterpret_cast<float4*>(&sIn[(r0 + i) * HID + c0 + 4]) =
                make_float4(t[i][4], t[i][5], t[i][6], t[i][7]);
        }
        __syncthreads();

        // stage 2: z = T @ W2 + b2
        #pragma unroll
        for (int i = 0; i < 4; i++)
            #pragma unroll
            for (int j = 0; j < 4; j++) acc[i][j] = bb2[j];
        #pragma unroll 2
        for (int k = 0; k < HID; k++) {
            const u64* wp = reinterpret_cast<const u64*>(&sW2[k * HID + c0]);
            u64 w0 = wp[0], w1 = wp[1], w2 = wp[2], w3 = wp[3];
            #pragma unroll
            for (int i = 0; i < 4; i++) {
                float a = sIn[(r0 + i) * HID + k];
                u64 a2 = pk2(a, a);
                acc[i][0] = fma2(a2, w0, acc[i][0]);
                acc[i][1] = fma2(a2, w1, acc[i][1]);
                acc[i][2] = fma2(a2, w2, acc[i][2]);
                acc[i][3] = fma2(a2, w3, acc[i][3]);
            }
        }
        #pragma unroll
        for (int i = 0; i < 4; i++) {
            int row = rbase + r0 + i;
            if (row < rend) {
                float z[8];
                #pragma unroll
                for (int j = 0; j < 4; j++) {
                    upk2(acc[i][j], z[2 * j], z[2 * j + 1]);
                }
                *reinterpret_cast<float4*>(&g_z[(size_t)row * HID + c0]) =
                    make_float4(z[0], z[1], z[2], z[3]);
                *reinterpret_cast<float4*>(&g_z[(size_t)row * HID + c0 + 4]) =
                    make_float4(z[4], z[5], z[6], z[7]);
                #pragma unroll
                for (int j = 0; j < 8; j++) {
                    ls[j] += z[j];
                    lss[j] += z[j] * z[j];
                }
            }
        }
        __syncthreads();
    }

    // block-level stats reduce in shared, one atomic per column per block
    #pragma unroll
    for (int j = 0; j < 8; j++) {
        sIn[tid * 8 + j] = ls[j];
        sIn[4096 + tid * 8 + j] = lss[j];
    }
    __syncthreads();
    if (tid < HID) {
        int c = tid;
        int tb = c >> 3;          // (tid & 15) owner group
        int j = c & 7;
        float s = 0.f, ss = 0.f;
        #pragma unroll
        for (int g = 0; g < 32; g++) {
            int t = tb + 16 * g;
            s += sIn[t * 8 + j];
            ss += sIn[4096 + t * 8 + j];
        }
        atomicAdd(&g_stats[c], s);
        atomicAdd(&g_stats[HID + c], ss);
    }
}

// ---------------- BN finalize + apply + relu -> h ---------------------------
__global__ void bn_kernel(const float* __restrict__ gamma,
                          const float* __restrict__ beta) {
    int i = blockIdx.x * blockDim.x + threadIdx.x;  // float4 index
    const int n4 = N_NODES * HID / 4;
    if (i >= n4) return;
    int c0 = (i & 31) * 4;
    float4 v = reinterpret_cast<const float4*>(g_z)[i];
    float va[4] = {v.x, v.y, v.z, v.w};
    float out[4];
    const float invN = 1.0f / (float)N_NODES;
    #pragma unroll
    for (int j = 0; j < 4; j++) {
        int c = c0 + j;
        float mean = g_stats[c] * invN;
        float var = g_stats[HID + c] * invN - mean * mean;
        float rstd = rsqrtf(var + BN_EPS);
        float o = gamma[c] * (va[j] - mean) * rstd + beta[c];
        out[j] = fmaxf(o, 0.f);
    }
    reinterpret_cast<float4*>(g_h)[i] = make_float4(out[0], out[1], out[2], out[3]);
}

// ---------------- global add pool -------------------------------------------
__global__ void pool_kernel(const int* __restrict__ batch) {
    int i = blockIdx.x * blockDim.x + threadIdx.x;
    if (i >= N_NODES * 32) return;
    int n = i >> 5;
    int q = i & 31;
    int gi = batch[n];
    float4 v = reinterpret_cast<const float4*>(g_h + (size_t)n * HID)[q];
    red_add_v4(g_pool + (size_t)gi * HID + 4 * q, v);
}

// ---------------- head: out = relu(g@W1+b1)@W2+b2 ---------------------------
__global__ void head_kernel(const float* __restrict__ w1, const float* __restrict__ b1,
                            const float* __restrict__ w2, const float* __restrict__ b2,
                            float* __restrict__ out) {
    __shared__ float srow[HID];
    __shared__ float st[HID];
    int gi = blockIdx.x;
    int c = threadIdx.x;
    srow[c] = g_pool[(size_t)gi * HID + c];
    __syncthreads();
    float acc = b1[c];
    for (int k = 0; k < HID; k++) acc += srow[k] * w1[k * HID + c];
    st[c] = fmaxf(acc, 0.f);
    __syncthreads();
    if (c < 2) {
        float o = b2[c];
        for (int k = 0; k < HID; k++) o += st[k] * w2[k * 2 + c];
        out[gi * 2 + c] = o;
    }
}

// ---------------- launch -----------------------------------------------------
extern "C" void kernel_launch(void* const* d_in, const int* in_sizes, int n_in,
                              void* d_out, int out_size) {
    const float* x        = (const float*)d_in[0];
    const int*   eidx     = (const int*)d_in[1];
    const float* eattr    = (const float*)d_in[2];
    const int*   batch    = (const int*)d_in[3];
    const float* node_w   = (const float*)d_in[4];
    const float* node_b   = (const float*)d_in[5];
    const float* edge_w   = (const float*)d_in[6];
    const float* edge_b   = (const float*)d_in[7];
    const float* mlp_w1   = (const float*)d_in[8];
    const float* mlp_b1   = (const float*)d_in[9];
    const float* mlp_w2   = (const float*)d_in[10];
    const float* mlp_b2   = (const float*)d_in[11];
    const float* bn_gamma = (const float*)d_in[12];
    const float* bn_beta  = (const float*)d_in[13];
    const float* head_w1  = (const float*)d_in[14];
    const float* head_b1  = (const float*)d_in[15];
    const float* head_w2  = (const float*)d_in[16];
    const float* head_b2  = (const float*)d_in[17];
    float* out = (float*)d_out;

    const int mlp_smem = MLP_SMEM_FLOATS * (int)sizeof(float);
    cudaFuncSetAttribute(mlp_kernel, cudaFuncAttributeMaxDynamicSharedMemorySize, mlp_smem);

    // node encoder -> g_h
    encoder_kernel<<<512, 256>>>(x, node_w, node_b);

    // CSR build (by dst), then edge encoder writes fp16 rows in CSR order
    zero_cnt_kernel<<<(N_NODES + 255) / 256, 256>>>();
    csr_count_kernel<<<(N_EDGES + 255) / 256, 256>>>(eidx);
    csr_scan_kernel<<<1, 1024>>>();
    csr_fill_kernel<<<(N_EDGES + 255) / 256, 256>>>(eidx);
    edge_encoder_kernel<<<2048, 256>>>(eattr, edge_w, edge_b);

    for (int l = 0; l < NLAYERS; l++) {
        zero_stats_kernel<<<1, 256>>>();
        agg_kernel<<<2048, 256>>>();
        mlp_kernel<<<148, MLP_THREADS, mlp_smem>>>(mlp_w1 + (size_t)l * HID * HID,
                                                   mlp_b1 + (size_t)l * HID,
                                                   mlp_w2 + (size_t)l * HID * HID,
                                                   mlp_b2 + (size_t)l * HID);
        bn_kernel<<<(N_NODES * HID / 4 + 255) / 256, 256>>>(bn_gamma + (size_t)l * HID,
                                                            bn_beta + (size_t)l * HID);
    }

    zero_pool_kernel<<<(NGRAPHS * HID + 255) / 256, 256>>>();
    pool_kernel<<<(N_NODES * 32 + 255) / 256, 256>>>(batch);
    head_kernel<<<NGRAPHS, HID>>>(head_w1, head_b1, head_w2, head_b2, out);
}

// round 5
// speedup vs baseline: 1.2412x; 1.2412x over previous
#include <cuda_runtime.h>
#include <cuda_fp16.h>

#define N_NODES 50000
#define N_EDGES 600000
#define HID 128
#define NODE_DIM 64
#define EDGE_DIM 16
#define NLAYERS 3
#define NGRAPHS 256
#define BN_EPS 1e-5f

typedef unsigned long long u64;

// ---------------- scratch (device globals; no allocations allowed) ----------
__device__ float g_h[N_NODES * HID];        // node features fp32
__device__ __half g_h16[N_NODES * HID];     // fp16 shadow for random gather
__device__ float g_zin[N_NODES * HID];      // h + agg (MLP input)
__device__ float g_z[N_NODES * HID];        // pre-BN MLP output
__device__ __half g_ea_h[N_EDGES * HID];    // encoded edge features, fp16, CSR order
__device__ float g_stats[2 * HID];          // column sums / sumsq
__device__ float g_pool[NGRAPHS * HID];     // pooled graph features
// CSR by destination
__device__ int g_cnt[N_NODES];
__device__ int g_off[N_NODES + 1];
__device__ int g_cur[N_NODES];
__device__ int g_csr_src[N_EDGES];
__device__ int g_slot[N_EDGES];             // edge e -> CSR slot
// parallel scan scratch
#define NCHUNK 1024
#define CHSZ ((N_NODES + NCHUNK - 1) / NCHUNK)   // 49
__device__ int g_chunk[NCHUNK];
__device__ int g_chunk_base[NCHUNK];

// ---------------- f32x2 packed helpers ---------------------------------------
__device__ __forceinline__ u64 pk2(float x, float y) {
    u64 r; asm("mov.b64 %0,{%1,%2};" : "=l"(r) : "f"(x), "f"(y)); return r;
}
__device__ __forceinline__ void upk2(u64 v, float& x, float& y) {
    asm("mov.b64 {%0,%1},%2;" : "=f"(x), "=f"(y) : "l"(v));
}
__device__ __forceinline__ u64 fma2(u64 a, u64 b, u64 c) {
    u64 d; asm("fma.rn.f32x2 %0,%1,%2,%3;" : "=l"(d) : "l"(a), "l"(b), "l"(c)); return d;
}

__device__ __forceinline__ void red_add_v4(float* p, float4 v) {
    asm volatile("red.global.add.v4.f32 [%0], {%1,%2,%3,%4};"
                 :: "l"(p), "f"(v.x), "f"(v.y), "f"(v.z), "f"(v.w) : "memory");
}

__device__ __forceinline__ float4 h16_load4(const __half* p) {
    uint2 u = *reinterpret_cast<const uint2*>(p);
    __half2 a = *reinterpret_cast<__half2*>(&u.x);
    __half2 b = *reinterpret_cast<__half2*>(&u.y);
    float2 fa = __half22float2(a);
    float2 fb = __half22float2(b);
    return make_float4(fa.x, fa.y, fb.x, fb.y);
}
__device__ __forceinline__ void h16_store4(__half* p, float4 v) {
    union { __half2 h[2]; uint2 u; } cv;
    cv.h[0] = __floats2half2_rn(v.x, v.y);
    cv.h[1] = __floats2half2_rn(v.z, v.w);
    *reinterpret_cast<uint2*>(p) = cv.u;
}

// ---------------- zero kernel (cnt + pool) -----------------------------------
__global__ void zero_cnt_pool_kernel() {
    int i = blockIdx.x * blockDim.x + threadIdx.x;
    if (i < N_NODES) g_cnt[i] = 0;
    if (i < NGRAPHS * HID) g_pool[i] = 0.f;
}

// ---------------- CSR build --------------------------------------------------
__global__ void csr_count_kernel(const int* __restrict__ eidx) {
    int e = blockIdx.x * blockDim.x + threadIdx.x;
    if (e < N_EDGES) atomicAdd(&g_cnt[eidx[N_EDGES + e]], 1);
}

// phase 1: per-chunk sums (8 blocks x 128 threads = 1024 chunk owners)
__global__ void chunk_sum_kernel() {
    int t = blockIdx.x * blockDim.x + threadIdx.x;
    if (t >= NCHUNK) return;
    int beg = t * CHSZ;
    int end = min(beg + CHSZ, N_NODES);
    int s = 0;
    for (int i = beg; i < end; i++) s += g_cnt[i];
    g_chunk[t] = s;
}

// phase 2: single-block scan of 1024 chunk sums (smem only)
__global__ void chunk_scan_kernel() {
    __shared__ int ssum[NCHUNK];
    int t = threadIdx.x;
    ssum[t] = g_chunk[t];
    __syncthreads();
    for (int off = 1; off < NCHUNK; off <<= 1) {
        int v = (t >= off) ? ssum[t - off] : 0;
        __syncthreads();
        ssum[t] += v;
        __syncthreads();
    }
    g_chunk_base[t] = (t == 0) ? 0 : ssum[t - 1];
    if (t == NCHUNK - 1) g_off[N_NODES] = ssum[t];
}

// phase 3: write offsets per chunk in parallel
__global__ void chunk_offs_kernel() {
    int t = blockIdx.x * blockDim.x + threadIdx.x;
    if (t >= NCHUNK) return;
    int beg = t * CHSZ;
    int end = min(beg + CHSZ, N_NODES);
    int run = g_chunk_base[t];
    for (int i = beg; i < end; i++) {
        g_off[i] = run;
        g_cur[i] = run;
        run += g_cnt[i];
    }
}

__global__ void csr_fill_kernel(const int* __restrict__ eidx) {
    int e = blockIdx.x * blockDim.x + threadIdx.x;
    if (e >= N_EDGES) return;
    int dst = eidx[N_EDGES + e];
    int slot = atomicAdd(&g_cur[dst], 1);
    g_csr_src[slot] = eidx[e];
    g_slot[e] = slot;
}

// ---------------- node encoder: h = x @ node_w + node_b ---------------------
__global__ void encoder_kernel(const float* __restrict__ x,
                               const float* __restrict__ W,
                               const float* __restrict__ b) {
    __shared__ float sW[NODE_DIM * HID];
    for (int i = threadIdx.x; i < NODE_DIM * HID; i += blockDim.x) sW[i] = W[i];
    __syncthreads();
    int lane = threadIdx.x & 31;
    int warp = (blockIdx.x * blockDim.x + threadIdx.x) >> 5;
    int nw = (gridDim.x * blockDim.x) >> 5;
    float4 bb = reinterpret_cast<const float4*>(b)[lane];
    for (int n = warp; n < N_NODES; n += nw) {
        const float4* xr = reinterpret_cast<const float4*>(x + (size_t)n * NODE_DIM);
        float4 acc = bb;
        #pragma unroll
        for (int kk = 0; kk < NODE_DIM / 4; kk++) {
            float4 xv = xr[kk];
            float xa[4] = {xv.x, xv.y, xv.z, xv.w};
            #pragma unroll
            for (int j = 0; j < 4; j++) {
                float4 w = *reinterpret_cast<const float4*>(&sW[(4 * kk + j) * HID + 4 * lane]);
                acc.x += xa[j] * w.x;
                acc.y += xa[j] * w.y;
                acc.z += xa[j] * w.z;
                acc.w += xa[j] * w.w;
            }
        }
        reinterpret_cast<float4*>(g_h + (size_t)n * HID)[lane] = acc;
        h16_store4(g_h16 + (size_t)n * HID + 4 * lane, acc);
    }
}

// ---- edge encoder (ONCE): ea = edge_attr @ edge_w + edge_b -> fp16, CSR order
__global__ void edge_encoder_kernel(const float* __restrict__ eattr,
                                    const float* __restrict__ W,
                                    const float* __restrict__ b) {
    __shared__ float sW[EDGE_DIM * HID];
    __shared__ float sb[HID];
    for (int i = threadIdx.x; i < EDGE_DIM * HID; i += blockDim.x) sW[i] = W[i];
    if (threadIdx.x < HID) sb[threadIdx.x] = b[threadIdx.x];
    __syncthreads();
    int lane = threadIdx.x & 31;
    int warp = (blockIdx.x * blockDim.x + threadIdx.x) >> 5;
    int nw = (gridDim.x * blockDim.x) >> 5;
    float4 bb = reinterpret_cast<const float4*>(sb)[lane];
    for (int e = warp; e < N_EDGES; e += nw) {
        const float4* ar = reinterpret_cast<const float4*>(eattr + (size_t)e * EDGE_DIM);
        float4 acc = bb;
        #pragma unroll
        for (int kk = 0; kk < EDGE_DIM / 4; kk++) {
            float4 av = ar[kk];
            float xa[4] = {av.x, av.y, av.z, av.w};
            #pragma unroll
            for (int j = 0; j < 4; j++) {
                float4 w = *reinterpret_cast<const float4*>(&sW[(4 * kk + j) * HID + 4 * lane]);
                acc.x += xa[j] * w.x;
                acc.y += xa[j] * w.y;
                acc.z += xa[j] * w.z;
                acc.w += xa[j] * w.w;
            }
        }
        int slot = __ldg(&g_slot[e]);
        h16_store4(g_ea_h + (size_t)slot * HID + 4 * lane, acc);
    }
}

// ---------------- aggregation: zin[n] = h[n] + sum_{e->n} relu(h16[src]+ea[e])
__global__ void agg_kernel() {
    // fused stats zero (mlp launches after agg completes)
    if (blockIdx.x == 0 && threadIdx.x < 2 * HID) g_stats[threadIdx.x] = 0.f;
    int lane = threadIdx.x & 31;
    int warp = (blockIdx.x * blockDim.x + threadIdx.x) >> 5;
    int nw = (gridDim.x * blockDim.x) >> 5;
    for (int n = warp; n < N_NODES; n += nw) {
        float4 acc = reinterpret_cast<const float4*>(g_h + (size_t)n * HID)[lane];
        int s = __ldg(&g_off[n]);
        int e = __ldg(&g_off[n + 1]);
        for (int idx = s; idx < e; idx++) {
            int src = __ldg(&g_csr_src[idx]);
            float4 hv = h16_load4(g_h16 + (size_t)src * HID + 4 * lane);
            float4 ev = h16_load4(g_ea_h + (size_t)idx * HID + 4 * lane);
            acc.x += fmaxf(hv.x + ev.x, 0.f);
            acc.y += fmaxf(hv.y + ev.y, 0.f);
            acc.z += fmaxf(hv.z + ev.z, 0.f);
            acc.w += fmaxf(hv.w + ev.w, 0.f);
        }
        reinterpret_cast<float4*>(g_zin + (size_t)n * HID)[lane] = acc;
    }
}

// ---------------- per-layer MLP: z = relu(zin@W1+b1)@W2+b2, + BN stats ------
// conflict-free f32x2 version: thread tile = 8 rows x 4 cols
// dyn smem (floats): W1[16384] W2[16384] In[16384] B1[128] B2[128]
#define TROWS 128
#define MLP_THREADS 512
#define MLP_SMEM_FLOATS (2 * HID * HID + TROWS * HID + 2 * HID)
__global__ __launch_bounds__(MLP_THREADS, 1)
void mlp_kernel(const float* __restrict__ W1, const float* __restrict__ B1,
                const float* __restrict__ W2, const float* __restrict__ B2) {
    extern __shared__ float sm[];
    float* sW1 = sm;
    float* sW2 = sm + HID * HID;
    float* sIn = sm + 2 * HID * HID;          // 128x128, reused for T and stats
    float* sB1 = sIn + TROWS * HID;
    float* sB2 = sB1 + HID;

    int tid = threadIdx.x;
    for (int i = tid; i < HID * HID; i += MLP_THREADS) { sW1[i] = W1[i]; sW2[i] = W2[i]; }
    if (tid < HID) { sB1[tid] = B1[tid]; sB2[tid] = B2[tid]; }
    __syncthreads();

    const int c0 = (tid & 31) * 4;   // 4 contiguous cols (conflict-free float4)
    const int r0 = (tid >> 5) * 8;   // 8 rows

    float4 bb1 = *reinterpret_cast<const float4*>(&sB1[c0]);
    float4 bb2 = *reinterpret_cast<const float4*>(&sB2[c0]);

    int rpb = (N_NODES + gridDim.x - 1) / gridDim.x;
    int base = blockIdx.x * rpb;
    int rend = min(base + rpb, N_NODES);

    float ls[4] = {0.f, 0.f, 0.f, 0.f};
    float lss[4] = {0.f, 0.f, 0.f, 0.f};

    for (int rbase = base; rbase < rend; rbase += TROWS) {
        // load input tile (128 rows x 128 cols)
        for (int i = tid; i < TROWS * HID / 4; i += MLP_THREADS) {
            int r = i >> 5;
            int q = i & 31;
            int row = rbase + r;
            float4 v = make_float4(0.f, 0.f, 0.f, 0.f);
            if (row < rend) v = reinterpret_cast<const float4*>(g_zin + (size_t)row * HID)[q];
            reinterpret_cast<float4*>(sIn)[i] = v;
        }
        __syncthreads();

        // stage 1: T = relu(In @ W1 + b1)
        u64 acc[8][2];
        #pragma unroll
        for (int i = 0; i < 8; i++) {
            acc[i][0] = pk2(bb1.x, bb1.y);
            acc[i][1] = pk2(bb1.z, bb1.w);
        }
        #pragma unroll 4
        for (int k = 0; k < HID; k++) {
            float4 w = *reinterpret_cast<const float4*>(&sW1[k * HID + c0]);
            u64 w0 = pk2(w.x, w.y), w1 = pk2(w.z, w.w);
            #pragma unroll
            for (int i = 0; i < 8; i++) {
                float a = sIn[(r0 + i) * HID + k];
                u64 a2 = pk2(a, a);
                acc[i][0] = fma2(a2, w0, acc[i][0]);
                acc[i][1] = fma2(a2, w1, acc[i][1]);
            }
        }
        __syncthreads();   // everyone done reading In
        #pragma unroll
        for (int i = 0; i < 8; i++) {
            float v0, v1, v2, v3;
            upk2(acc[i][0], v0, v1);
            upk2(acc[i][1], v2, v3);
            *reinterpret_cast<float4*>(&sIn[(r0 + i) * HID + c0]) =
                make_float4(fmaxf(v0, 0.f), fmaxf(v1, 0.f), fmaxf(v2, 0.f), fmaxf(v3, 0.f));
        }
        __syncthreads();

        // stage 2: z = T @ W2 + b2
        #pragma unroll
        for (int i = 0; i < 8; i++) {
            acc[i][0] = pk2(bb2.x, bb2.y);
            acc[i][1] = pk2(bb2.z, bb2.w);
        }
        #pragma unroll 4
        for (int k = 0; k < HID; k++) {
            float4 w = *reinterpret_cast<const float4*>(&sW2[k * HID + c0]);
            u64 w0 = pk2(w.x, w.y), w1 = pk2(w.z, w.w);
            #pragma unroll
            for (int i = 0; i < 8; i++) {
                float a = sIn[(r0 + i) * HID + k];
                u64 a2 = pk2(a, a);
                acc[i][0] = fma2(a2, w0, acc[i][0]);
                acc[i][1] = fma2(a2, w1, acc[i][1]);
            }
        }
        #pragma unroll
        for (int i = 0; i < 8; i++) {
            int row = rbase + r0 + i;
            if (row < rend) {
                float z0, z1, z2, z3;
                upk2(acc[i][0], z0, z1);
                upk2(acc[i][1], z2, z3);
                *reinterpret_cast<float4*>(&g_z[(size_t)row * HID + c0]) =
                    make_float4(z0, z1, z2, z3);
                ls[0] += z0; lss[0] += z0 * z0;
                ls[1] += z1; lss[1] += z1 * z1;
                ls[2] += z2; lss[2] += z2 * z2;
                ls[3] += z3; lss[3] += z3 * z3;
            }
        }
        __syncthreads();
    }

    // block-level stats reduce in shared, one atomic per column per block
    #pragma unroll
    for (int j = 0; j < 4; j++) {
        sIn[tid * 4 + j] = ls[j];
        sIn[2048 + tid * 4 + j] = lss[j];
    }
    __syncthreads();
    if (tid < HID) {
        int c = tid;
        int cq = c >> 2;          // owning thread's (tid & 31)
        int j = c & 3;
        float s = 0.f, ss = 0.f;
        #pragma unroll
        for (int g = 0; g < 16; g++) {
            int t = cq + 32 * g;
            s += sIn[t * 4 + j];
            ss += sIn[2048 + t * 4 + j];
        }
        atomicAdd(&g_stats[c], s);
        atomicAdd(&g_stats[HID + c], ss);
    }
}

// ---------------- BN finalize + apply + relu -> h (+h16) --------------------
__global__ void bn_kernel(const float* __restrict__ gamma,
                          const float* __restrict__ beta) {
    int i = blockIdx.x * blockDim.x + threadIdx.x;  // float4 index
    const int n4 = N_NODES * HID / 4;
    if (i >= n4) return;
    int c0 = (i & 31) * 4;
    float4 v = reinterpret_cast<const float4*>(g_z)[i];
    float va[4] = {v.x, v.y, v.z, v.w};
    float out[4];
    const float invN = 1.0f / (float)N_NODES;
    #pragma unroll
    for (int j = 0; j < 4; j++) {
        int c = c0 + j;
        float mean = g_stats[c] * invN;
        float var = g_stats[HID + c] * invN - mean * mean;
        float rstd = rsqrtf(var + BN_EPS);
        float o = gamma[c] * (va[j] - mean) * rstd + beta[c];
        out[j] = fmaxf(o, 0.f);
    }
    float4 ov = make_float4(out[0], out[1], out[2], out[3]);
    reinterpret_cast<float4*>(g_h)[i] = ov;
    h16_store4(g_h16 + (size_t)i * 4, ov);
}

// ---------------- last layer: BN + relu + pool (no h write) ------------------
__global__ void bn_pool_kernel(const float* __restrict__ gamma,
                               const float* __restrict__ beta,
                               const int* __restrict__ batch) {
    int i = blockIdx.x * blockDim.x + threadIdx.x;  // float4 index
    const int n4 = N_NODES * HID / 4;
    if (i >= n4) return;
    int n = i >> 5;
    int c0 = (i & 31) * 4;
    float4 v = reinterpret_cast<const float4*>(g_z)[i];
    float va[4] = {v.x, v.y, v.z, v.w};
    float out[4];
    const float invN = 1.0f / (float)N_NODES;
    #pragma unroll
    for (int j = 0; j < 4; j++) {
        int c = c0 + j;
        float mean = g_stats[c] * invN;
        float var = g_stats[HID + c] * invN - mean * mean;
        float rstd = rsqrtf(var + BN_EPS);
        float o = gamma[c] * (va[j] - mean) * rstd + beta[c];
        out[j] = fmaxf(o, 0.f);
    }
    int gi = __ldg(&batch[n]);
    red_add_v4(g_pool + (size_t)gi * HID + c0,
               make_float4(out[0], out[1], out[2], out[3]));
}

// ---------------- head: out = relu(g@W1+b1)@W2+b2 ---------------------------
__global__ void head_kernel(const float* __restrict__ w1, const float* __restrict__ b1,
                            const float* __restrict__ w2, const float* __restrict__ b2,
                            float* __restrict__ out) {
    __shared__ float srow[HID];
    __shared__ float st[HID];
    int gi = blockIdx.x;
    int c = threadIdx.x;
    srow[c] = g_pool[(size_t)gi * HID + c];
    __syncthreads();
    float acc = b1[c];
    for (int k = 0; k < HID; k++) acc += srow[k] * w1[k * HID + c];
    st[c] = fmaxf(acc, 0.f);
    __syncthreads();
    if (c < 2) {
        float o = b2[c];
        for (int k = 0; k < HID; k++) o += st[k] * w2[k * 2 + c];
        out[gi * 2 + c] = o;
    }
}

// ---------------- launch -----------------------------------------------------
extern "C" void kernel_launch(void* const* d_in, const int* in_sizes, int n_in,
                              void* d_out, int out_size) {
    const float* x        = (const float*)d_in[0];
    const int*   eidx     = (const int*)d_in[1];
    const float* eattr    = (const float*)d_in[2];
    const int*   batch    = (const int*)d_in[3];
    const float* node_w   = (const float*)d_in[4];
    const float* node_b   = (const float*)d_in[5];
    const float* edge_w   = (const float*)d_in[6];
    const float* edge_b   = (const float*)d_in[7];
    const float* mlp_w1   = (const float*)d_in[8];
    const float* mlp_b1   = (const float*)d_in[9];
    const float* mlp_w2   = (const float*)d_in[10];
    const float* mlp_b2   = (const float*)d_in[11];
    const float* bn_gamma = (const float*)d_in[12];
    const float* bn_beta  = (const float*)d_in[13];
    const float* head_w1  = (const float*)d_in[14];
    const float* head_b1  = (const float*)d_in[15];
    const float* head_w2  = (const float*)d_in[16];
    const float* head_b2  = (const float*)d_in[17];
    float* out = (float*)d_out;

    const int mlp_smem = MLP_SMEM_FLOATS * (int)sizeof(float);
    cudaFuncSetAttribute(mlp_kernel, cudaFuncAttributeMaxDynamicSharedMemorySize, mlp_smem);

    // node encoder -> g_h, g_h16
    encoder_kernel<<<512, 256>>>(x, node_w, node_b);

    // CSR build (by dst) with parallel scan; edge encoder writes fp16 CSR order
    zero_cnt_pool_kernel<<<(N_NODES + 255) / 256, 256>>>();
    csr_count_kernel<<<(N_EDGES + 255) / 256, 256>>>(eidx);
    chunk_sum_kernel<<<NCHUNK / 128, 128>>>();
    chunk_scan_kernel<<<1, NCHUNK>>>();
    chunk_offs_kernel<<<NCHUNK / 128, 128>>>();
    csr_fill_kernel<<<(N_EDGES + 255) / 256, 256>>>(eidx);
    edge_encoder_kernel<<<2048, 256>>>(eattr, edge_w, edge_b);

    for (int l = 0; l < NLAYERS; l++) {
        agg_kernel<<<2048, 256>>>();
        mlp_kernel<<<148, MLP_THREADS, mlp_smem>>>(mlp_w1 + (size_t)l * HID * HID,
                                                   mlp_b1 + (size_t)l * HID,
                                                   mlp_w2 + (size_t)l * HID * HID,
                                                   mlp_b2 + (size_t)l * HID);
        if (l < NLAYERS - 1) {
            bn_kernel<<<(N_NODES * HID / 4 + 255) / 256, 256>>>(
                bn_gamma + (size_t)l * HID, bn_beta + (size_t)l * HID);
        } else {
            bn_pool_kernel<<<(N_NODES * HID / 4 + 255) / 256, 256>>>(
                bn_gamma + (size_t)l * HID, bn_beta + (size_t)l * HID, batch);
        }
    }

    head_kernel<<<NGRAPHS, HID>>>(head_w1, head_b1, head_w2, head_b2, out);
}

// round 6
// speedup vs baseline: 1.2804x; 1.0316x over previous
#include <cuda_runtime.h>
#include <cuda_fp16.h>

#define N_NODES 50000
#define N_EDGES 600000
#define HID 128
#define NODE_DIM 64
#define EDGE_DIM 16
#define NLAYERS 3
#define NGRAPHS 256
#define BN_EPS 1e-5f

typedef unsigned long long u64;

// ---------------- scratch (device globals; no allocations allowed) ----------
__device__ __half g_z16[N_NODES * HID];    // node features / pre-BN z, fp16
__device__ float g_zin[N_NODES * HID];     // h + agg (MLP input), fp32
__device__ __half g_ea_h[N_EDGES * HID];   // encoded edge features, fp16, CSR order
__device__ float g_stats[NLAYERS * 2 * HID]; // per-layer column sums / sumsq
__device__ float g_pool[NGRAPHS * HID];    // pooled graph features
// CSR by destination
__device__ int g_cnt[N_NODES];
__device__ int g_off[N_NODES + 1];
__device__ int g_cur[N_NODES];
__device__ int g_csr_src[N_EDGES];
// parallel scan scratch
#define NCHUNK 1024
#define CHSZ ((N_NODES + NCHUNK - 1) / NCHUNK)
__device__ int g_chunk[NCHUNK];
__device__ int g_chunk_base[NCHUNK];

// ---------------- f32x2 packed helpers ---------------------------------------
__device__ __forceinline__ u64 pk2(float x, float y) {
    u64 r; asm("mov.b64 %0,{%1,%2};" : "=l"(r) : "f"(x), "f"(y)); return r;
}
__device__ __forceinline__ void upk2(u64 v, float& x, float& y) {
    asm("mov.b64 {%0,%1},%2;" : "=f"(x), "=f"(y) : "l"(v));
}
__device__ __forceinline__ u64 fma2(u64 a, u64 b, u64 c) {
    u64 d; asm("fma.rn.f32x2 %0,%1,%2,%3;" : "=l"(d) : "l"(a), "l"(b), "l"(c)); return d;
}

__device__ __forceinline__ void red_add_v4(float* p, float4 v) {
    asm volatile("red.global.add.v4.f32 [%0], {%1,%2,%3,%4};"
                 :: "l"(p), "f"(v.x), "f"(v.y), "f"(v.z), "f"(v.w) : "memory");
}

__device__ __forceinline__ float4 h16_load4(const __half* p) {
    uint2 u = *reinterpret_cast<const uint2*>(p);
    __half2 a = *reinterpret_cast<__half2*>(&u.x);
    __half2 b = *reinterpret_cast<__half2*>(&u.y);
    float2 fa = __half22float2(a);
    float2 fb = __half22float2(b);
    return make_float4(fa.x, fa.y, fb.x, fb.y);
}
__device__ __forceinline__ void h16_store4(__half* p, float4 v) {
    union { __half2 h[2]; uint2 u; } cv;
    cv.h[0] = __floats2half2_rn(v.x, v.y);
    cv.h[1] = __floats2half2_rn(v.z, v.w);
    *reinterpret_cast<uint2*>(p) = cv.u;
}

// ---------------- node encoder: z16 = x @ node_w + node_b; also zeros -------
__global__ void encoder_kernel(const float* __restrict__ x,
                               const float* __restrict__ W,
                               const float* __restrict__ b) {
    // fused zeroing of cnt / pool / stats (kernel boundary orders vs consumers)
    int gt = blockIdx.x * blockDim.x + threadIdx.x;
    int gsz = gridDim.x * blockDim.x;
    for (int i = gt; i < N_NODES; i += gsz) g_cnt[i] = 0;
    for (int i = gt; i < NGRAPHS * HID; i += gsz) g_pool[i] = 0.f;
    for (int i = gt; i < NLAYERS * 2 * HID; i += gsz) g_stats[i] = 0.f;

    __shared__ float sW[NODE_DIM * HID];
    for (int i = threadIdx.x; i < NODE_DIM * HID; i += blockDim.x) sW[i] = W[i];
    __syncthreads();
    int lane = threadIdx.x & 31;
    int warp = gt >> 5;
    int nw = gsz >> 5;
    float4 bb = reinterpret_cast<const float4*>(b)[lane];
    for (int n = warp; n < N_NODES; n += nw) {
        const float4* xr = reinterpret_cast<const float4*>(x + (size_t)n * NODE_DIM);
        float4 acc = bb;
        #pragma unroll
        for (int kk = 0; kk < NODE_DIM / 4; kk++) {
            float4 xv = xr[kk];
            float xa[4] = {xv.x, xv.y, xv.z, xv.w};
            #pragma unroll
            for (int j = 0; j < 4; j++) {
                float4 w = *reinterpret_cast<const float4*>(&sW[(4 * kk + j) * HID + 4 * lane]);
                acc.x += xa[j] * w.x;
                acc.y += xa[j] * w.y;
                acc.z += xa[j] * w.z;
                acc.w += xa[j] * w.w;
            }
        }
        h16_store4(g_z16 + (size_t)n * HID + 4 * lane, acc);
    }
}

// ---------------- CSR build --------------------------------------------------
__global__ void csr_count_kernel(const int* __restrict__ eidx) {
    int e = blockIdx.x * blockDim.x + threadIdx.x;
    if (e < N_EDGES) atomicAdd(&g_cnt[eidx[N_EDGES + e]], 1);
}

__global__ void chunk_sum_kernel() {
    int t = blockIdx.x * blockDim.x + threadIdx.x;
    if (t >= NCHUNK) return;
    int beg = t * CHSZ;
    int end = min(beg + CHSZ, N_NODES);
    int s = 0;
    for (int i = beg; i < end; i++) s += g_cnt[i];
    g_chunk[t] = s;
}

__global__ void chunk_scan_kernel() {
    __shared__ int ssum[NCHUNK];
    int t = threadIdx.x;
    ssum[t] = g_chunk[t];
    __syncthreads();
    for (int off = 1; off < NCHUNK; off <<= 1) {
        int v = (t >= off) ? ssum[t - off] : 0;
        __syncthreads();
        ssum[t] += v;
        __syncthreads();
    }
    g_chunk_base[t] = (t == 0) ? 0 : ssum[t - 1];
    if (t == NCHUNK - 1) g_off[N_NODES] = ssum[t];
}

__global__ void chunk_offs_kernel() {
    int t = blockIdx.x * blockDim.x + threadIdx.x;
    if (t >= NCHUNK) return;
    int beg = t * CHSZ;
    int end = min(beg + CHSZ, N_NODES);
    int run = g_chunk_base[t];
    for (int i = beg; i < end; i++) {
        g_off[i] = run;
        g_cur[i] = run;
        run += g_cnt[i];
    }
}

// --- fused: csr_fill + edge encoder -> fp16 rows in CSR order ---------------
__global__ void edge_enc_fill_kernel(const float* __restrict__ eattr,
                                     const int* __restrict__ eidx,
                                     const float* __restrict__ W,
                                     const float* __restrict__ b) {
    __shared__ float sW[EDGE_DIM * HID];
    __shared__ float sb[HID];
    for (int i = threadIdx.x; i < EDGE_DIM * HID; i += blockDim.x) sW[i] = W[i];
    if (threadIdx.x < HID) sb[threadIdx.x] = b[threadIdx.x];
    __syncthreads();
    int lane = threadIdx.x & 31;
    int warp = (blockIdx.x * blockDim.x + threadIdx.x) >> 5;
    int nw = (gridDim.x * blockDim.x) >> 5;
    float4 bb = reinterpret_cast<const float4*>(sb)[lane];
    for (int e = warp; e < N_EDGES; e += nw) {
        int slot = 0;
        if (lane == 0) {
            int src = eidx[e];
            int dst = eidx[N_EDGES + e];
            slot = atomicAdd(&g_cur[dst], 1);
            g_csr_src[slot] = src;
        }
        slot = __shfl_sync(0xffffffffu, slot, 0);
        const float4* ar = reinterpret_cast<const float4*>(eattr + (size_t)e * EDGE_DIM);
        float4 acc = bb;
        #pragma unroll
        for (int kk = 0; kk < EDGE_DIM / 4; kk++) {
            float4 av = ar[kk];
            float xa[4] = {av.x, av.y, av.z, av.w};
            #pragma unroll
            for (int j = 0; j < 4; j++) {
                float4 w = *reinterpret_cast<const float4*>(&sW[(4 * kk + j) * HID + 4 * lane]);
                acc.x += xa[j] * w.x;
                acc.y += xa[j] * w.y;
                acc.z += xa[j] * w.z;
                acc.w += xa[j] * w.w;
            }
        }
        h16_store4(g_ea_h + (size_t)slot * HID + 4 * lane, acc);
    }
}

// ---- aggregation with inline BN of previous layer ---------------------------
// zin[n] = h[n] + sum_{e->n} relu(h[src] + ea[e]),
// where h = BN ? relu(scale*z16 + shift) : z16 (encoder output, no relu)
template<bool BN>
__global__ void agg_kernel(const float* __restrict__ gamma,
                           const float* __restrict__ beta,
                           const float* __restrict__ stats) {
    __shared__ float s_sc[HID], s_sh[HID];
    if (BN) {
        if (threadIdx.x < HID) {
            int c = threadIdx.x;
            const float invN = 1.0f / (float)N_NODES;
            float mean = stats[c] * invN;
            float var = stats[HID + c] * invN - mean * mean;
            float rstd = rsqrtf(var + BN_EPS);
            float sc = gamma[c] * rstd;
            s_sc[c] = sc;
            s_sh[c] = beta[c] - sc * mean;
        }
        __syncthreads();
    }
    int lane = threadIdx.x & 31;
    int warp = (blockIdx.x * blockDim.x + threadIdx.x) >> 5;
    int nw = (gridDim.x * blockDim.x) >> 5;
    float4 sc4 = make_float4(1.f, 1.f, 1.f, 1.f), sh4 = make_float4(0.f, 0.f, 0.f, 0.f);
    if (BN) {
        sc4 = *reinterpret_cast<const float4*>(&s_sc[4 * lane]);
        sh4 = *reinterpret_cast<const float4*>(&s_sh[4 * lane]);
    }
    for (int n = warp; n < N_NODES; n += nw) {
        float4 z = h16_load4(g_z16 + (size_t)n * HID + 4 * lane);
        float4 acc;
        if (BN) {
            acc.x = fmaxf(fmaf(z.x, sc4.x, sh4.x), 0.f);
            acc.y = fmaxf(fmaf(z.y, sc4.y, sh4.y), 0.f);
            acc.z = fmaxf(fmaf(z.z, sc4.z, sh4.z), 0.f);
            acc.w = fmaxf(fmaf(z.w, sc4.w, sh4.w), 0.f);
        } else {
            acc = z;
        }
        int s = __ldg(&g_off[n]);
        int e = __ldg(&g_off[n + 1]);
        for (int idx = s; idx < e; idx++) {
            int src = __ldg(&g_csr_src[idx]);
            float4 hv = h16_load4(g_z16 + (size_t)src * HID + 4 * lane);
            if (BN) {
                hv.x = fmaxf(fmaf(hv.x, sc4.x, sh4.x), 0.f);
                hv.y = fmaxf(fmaf(hv.y, sc4.y, sh4.y), 0.f);
                hv.z = fmaxf(fmaf(hv.z, sc4.z, sh4.z), 0.f);
                hv.w = fmaxf(fmaf(hv.w, sc4.w, sh4.w), 0.f);
            }
            float4 ev = h16_load4(g_ea_h + (size_t)idx * HID + 4 * lane);
            acc.x += fmaxf(hv.x + ev.x, 0.f);
            acc.y += fmaxf(hv.y + ev.y, 0.f);
            acc.z += fmaxf(hv.z + ev.z, 0.f);
            acc.w += fmaxf(hv.w + ev.w, 0.f);
        }
        reinterpret_cast<float4*>(g_zin + (size_t)n * HID)[lane] = acc;
    }
}

// ---------------- per-layer MLP: z16 = relu(zin@W1+b1)@W2+b2, + BN stats ----
// thread tile: rows = lane + 32*i (i<4), cols = wid*8 .. wid*8+7
// smem tile padded stride 129 -> conflict-free LDS.32 a-loads, broadcast w.
#define TSTR 129
#define MLP_THREADS 512
#define MLP_SMEM_FLOATS (2 * HID * HID + HID * TSTR + 2 * HID)
__global__ __launch_bounds__(MLP_THREADS, 1)
void mlp_kernel(const float* __restrict__ W1, const float* __restrict__ B1,
                const float* __restrict__ W2, const float* __restrict__ B2,
                float* __restrict__ stats) {
    extern __shared__ float sm[];
    float* sW1 = sm;
    float* sW2 = sm + HID * HID;
    float* sT  = sm + 2 * HID * HID;          // 128 x 129 padded tile (In, then T)
    float* sB1 = sT + HID * TSTR;
    float* sB2 = sB1 + HID;

    int tid = threadIdx.x;
    int lane = tid & 31;
    int wid = tid >> 5;
    for (int i = tid; i < HID * HID; i += MLP_THREADS) { sW1[i] = W1[i]; sW2[i] = W2[i]; }
    if (tid < HID) { sB1[tid] = B1[tid]; sB2[tid] = B2[tid]; }
    __syncthreads();

    const int c0 = wid * 8;

    u64 bb1[4], bb2[4];
    #pragma unroll
    for (int j = 0; j < 4; j++) {
        bb1[j] = pk2(sB1[c0 + 2 * j], sB1[c0 + 2 * j + 1]);
        bb2[j] = pk2(sB2[c0 + 2 * j], sB2[c0 + 2 * j + 1]);
    }

    int rpb = (N_NODES + gridDim.x - 1) / gridDim.x;
    int base = blockIdx.x * rpb;
    int rend = min(base + rpb, N_NODES);

    float ls[8], lss[8];
    #pragma unroll
    for (int j = 0; j < 8; j++) { ls[j] = 0.f; lss[j] = 0.f; }

    for (int rbase = base; rbase < rend; rbase += HID) {
        // load input tile into padded smem
        for (int i = tid; i < HID * 32; i += MLP_THREADS) {
            int r = i >> 5;
            int q = i & 31;
            int row = rbase + r;
            float4 v = make_float4(0.f, 0.f, 0.f, 0.f);
            if (row < rend) v = reinterpret_cast<const float4*>(g_zin + (size_t)row * HID)[q];
            float* dst = &sT[r * TSTR + 4 * q];
            dst[0] = v.x; dst[1] = v.y; dst[2] = v.z; dst[3] = v.w;
        }
        __syncthreads();

        // stage 1: T = relu(In @ W1 + b1)
        u64 acc[4][4];
        #pragma unroll
        for (int i = 0; i < 4; i++)
            #pragma unroll
            for (int j = 0; j < 4; j++) acc[i][j] = bb1[j];
        #pragma unroll 4
        for (int k = 0; k < HID; k++) {
            float4 wa = *reinterpret_cast<const float4*>(&sW1[k * HID + c0]);
            float4 wb = *reinterpret_cast<const float4*>(&sW1[k * HID + c0 + 4]);
            u64 w0 = pk2(wa.x, wa.y), w1 = pk2(wa.z, wa.w);
            u64 w2 = pk2(wb.x, wb.y), w3 = pk2(wb.z, wb.w);
            #pragma unroll
            for (int i = 0; i < 4; i++) {
                float a = sT[(lane + 32 * i) * TSTR + k];
                u64 a2 = pk2(a, a);
                acc[i][0] = fma2(a2, w0, acc[i][0]);
                acc[i][1] = fma2(a2, w1, acc[i][1]);
                acc[i][2] = fma2(a2, w2, acc[i][2]);
                acc[i][3] = fma2(a2, w3, acc[i][3]);
            }
        }
        float t[4][8];
        #pragma unroll
        for (int i = 0; i < 4; i++)
            #pragma unroll
            for (int j = 0; j < 4; j++) {
                float v0, v1;
                upk2(acc[i][j], v0, v1);
                t[i][2 * j] = fmaxf(v0, 0.f);
                t[i][2 * j + 1] = fmaxf(v1, 0.f);
            }
        __syncthreads();   // all reads of In done
        #pragma unroll
        for (int i = 0; i < 4; i++) {
            float* dst = &sT[(lane + 32 * i) * TSTR + c0];
            #pragma unroll
            for (int j = 0; j < 8; j++) dst[j] = t[i][j];
        }
        __syncthreads();

        // stage 2: z = T @ W2 + b2
        #pragma unroll
        for (int i = 0; i < 4; i++)
            #pragma unroll
            for (int j = 0; j < 4; j++) acc[i][j] = bb2[j];
        #pragma unroll 4
        for (int k = 0; k < HID; k++) {
            float4 wa = *reinterpret_cast<const float4*>(&sW2[k * HID + c0]);
            float4 wb = *reinterpret_cast<const float4*>(&sW2[k * HID + c0 + 4]);
            u64 w0 = pk2(wa.x, wa.y), w1 = pk2(wa.z, wa.w);
            u64 w2 = pk2(wb.x, wb.y), w3 = pk2(wb.z, wb.w);
            #pragma unroll
            for (int i = 0; i < 4; i++) {
                float a = sT[(lane + 32 * i) * TSTR + k];
                u64 a2 = pk2(a, a);
                acc[i][0] = fma2(a2, w0, acc[i][0]);
                acc[i][1] = fma2(a2, w1, acc[i][1]);
                acc[i][2] = fma2(a2, w2, acc[i][2]);
                acc[i][3] = fma2(a2, w3, acc[i][3]);
            }
        }
        #pragma unroll
        for (int i = 0; i < 4; i++) {
            int row = rbase + lane + 32 * i;
            if (row < rend) {
                float z[8];
                #pragma unroll
                for (int j = 0; j < 4; j++) upk2(acc[i][j], z[2 * j], z[2 * j + 1]);
                union { __half2 h[4]; uint4 u; } cv;
                cv.h[0] = __floats2half2_rn(z[0], z[1]);
                cv.h[1] = __floats2half2_rn(z[2], z[3]);
                cv.h[2] = __floats2half2_rn(z[4], z[5]);
                cv.h[3] = __floats2half2_rn(z[6], z[7]);
                *reinterpret_cast<uint4*>(g_z16 + (size_t)row * HID + c0) = cv.u;
                #pragma unroll
                for (int j = 0; j < 8; j++) {
                    ls[j] += z[j];
                    lss[j] += z[j] * z[j];
                }
            }
        }
        __syncthreads();
    }

    // warp-reduce stats across lanes (cols are warp-uniform), lane0 atomics
    #pragma unroll
    for (int j = 0; j < 8; j++) {
        #pragma unroll
        for (int o = 16; o > 0; o >>= 1) {
            ls[j]  += __shfl_down_sync(0xffffffffu, ls[j], o);
            lss[j] += __shfl_down_sync(0xffffffffu, lss[j], o);
        }
    }
    if (lane == 0) {
        #pragma unroll
        for (int j = 0; j < 8; j++) {
            atomicAdd(&stats[c0 + j], ls[j]);
            atomicAdd(&stats[HID + c0 + j], lss[j]);
        }
    }
}

// ---------------- last layer: BN + relu + pool (reads z16) ------------------
__global__ void bn_pool_kernel(const float* __restrict__ gamma,
                               const float* __restrict__ beta,
                               const float* __restrict__ stats,
                               const int* __restrict__ batch) {
    int i = blockIdx.x * blockDim.x + threadIdx.x;  // float4-group index
    const int n4 = N_NODES * HID / 4;
    if (i >= n4) return;
    int n = i >> 5;
    int c0 = (i & 31) * 4;
    float4 z = h16_load4(g_z16 + (size_t)i * 4);
    float za[4] = {z.x, z.y, z.z, z.w};
    float out[4];
    const float invN = 1.0f / (float)N_NODES;
    #pragma unroll
    for (int j = 0; j < 4; j++) {
        int c = c0 + j;
        float mean = stats[c] * invN;
        float var = stats[HID + c] * invN - mean * mean;
        float rstd = rsqrtf(var + BN_EPS);
        float o = gamma[c] * (za[j] - mean) * rstd + beta[c];
        out[j] = fmaxf(o, 0.f);
    }
    int gi = __ldg(&batch[n]);
    red_add_v4(g_pool + (size_t)gi * HID + c0,
               make_float4(out[0], out[1], out[2], out[3]));
}

// ---------------- head: out = relu(g@W1+b1)@W2+b2 ---------------------------
__global__ void head_kernel(const float* __restrict__ w1, const float* __restrict__ b1,
                            const float* __restrict__ w2, const float* __restrict__ b2,
                            float* __restrict__ out) {
    __shared__ float srow[HID];
    __shared__ float st[HID];
    int gi = blockIdx.x;
    int c = threadIdx.x;
    srow[c] = g_pool[(size_t)gi * HID + c];
    __syncthreads();
    float acc = b1[c];
    for (int k = 0; k < HID; k++) acc += srow[k] * w1[k * HID + c];
    st[c] = fmaxf(acc, 0.f);
    __syncthreads();
    if (c < 2) {
        float o = b2[c];
        for (int k = 0; k < HID; k++) o += st[k] * w2[k * 2 + c];
        out[gi * 2 + c] = o;
    }
}

// ---------------- launch -----------------------------------------------------
extern "C" void kernel_launch(void* const* d_in, const int* in_sizes, int n_in,
                              void* d_out, int out_size) {
    const float* x        = (const float*)d_in[0];
    const int*   eidx     = (const int*)d_in[1];
    const float* eattr    = (const float*)d_in[2];
    const int*   batch    = (const int*)d_in[3];
    const float* node_w   = (const float*)d_in[4];
    const float* node_b   = (const float*)d_in[5];
    const float* edge_w   = (const float*)d_in[6];
    const float* edge_b   = (const float*)d_in[7];
    const float* mlp_w1   = (const float*)d_in[8];
    const float* mlp_b1   = (const float*)d_in[9];
    const float* mlp_w2   = (const float*)d_in[10];
    const float* mlp_b2   = (const float*)d_in[11];
    const float* bn_gamma = (const float*)d_in[12];
    const float* bn_beta  = (const float*)d_in[13];
    const float* head_w1  = (const float*)d_in[14];
    const float* head_b1  = (const float*)d_in[15];
    const float* head_w2  = (const float*)d_in[16];
    const float* head_b2  = (const float*)d_in[17];
    float* out = (float*)d_out;

    const int mlp_smem = MLP_SMEM_FLOATS * (int)sizeof(float);
    cudaFuncSetAttribute(mlp_kernel, cudaFuncAttributeMaxDynamicSharedMemorySize, mlp_smem);

    float* d_stats;
    cudaGetSymbolAddress((void**)&d_stats, g_stats);

    // encoder (also zeros cnt/pool/stats) -> z16
    encoder_kernel<<<512, 256>>>(x, node_w, node_b);

    // CSR build (parallel scan), then fused fill + edge encoder
    csr_count_kernel<<<(N_EDGES + 255) / 256, 256>>>(eidx);
    chunk_sum_kernel<<<NCHUNK / 128, 128>>>();
    chunk_scan_kernel<<<1, NCHUNK>>>();
    chunk_offs_kernel<<<NCHUNK / 128, 128>>>();
    edge_enc_fill_kernel<<<2048, 256>>>(eattr, eidx, edge_w, edge_b);

    for (int l = 0; l < NLAYERS; l++) {
        if (l == 0) {
            agg_kernel<false><<<2048, 256>>>(nullptr, nullptr, nullptr);
        } else {
            agg_kernel<true><<<2048, 256>>>(bn_gamma + (size_t)(l - 1) * HID,
                                            bn_beta + (size_t)(l - 1) * HID,
                                            d_stats + (size_t)(l - 1) * 2 * HID);
        }
        mlp_kernel<<<148, MLP_THREADS, mlp_smem>>>(mlp_w1 + (size_t)l * HID * HID,
                                                   mlp_b1 + (size_t)l * HID,
                                                   mlp_w2 + (size_t)l * HID * HID,
                                                   mlp_b2 + (size_t)l * HID,
                                                   d_stats + (size_t)l * 2 * HID);
    }

    bn_pool_kernel<<<(N_NODES * HID / 4 + 255) / 256, 256>>>(
        bn_gamma + (size_t)(NLAYERS - 1) * HID,
        bn_beta + (size_t)(NLAYERS - 1) * HID,
        d_stats + (size_t)(NLAYERS - 1) * 2 * HID, batch);
    head_kernel<<<NGRAPHS, HID>>>(head_w1, head_b1, head_w2, head_b2, out);
}

// round 8
// speedup vs baseline: 1.3406x; 1.0470x over previous
#include <cuda_runtime.h>
#include <cuda_fp16.h>

#define N_NODES 50000
#define N_EDGES 600000
#define HID 128
#define NODE_DIM 64
#define EDGE_DIM 16
#define NLAYERS 3
#define NGRAPHS 256
#define BN_EPS 1e-5f

typedef unsigned long long u64;

// ---------------- scratch (device globals; no allocations allowed) ----------
__device__ __half g_z16[N_NODES * HID];    // node features / pre-BN z, fp16
__device__ __half g_zin16[N_NODES * HID];  // h + agg (MLP input), fp16
__device__ __half g_ea_h[N_EDGES * HID];   // encoded edge features, fp16, CSR order
__device__ float g_stats[NLAYERS * 2 * HID]; // per-layer column sums / sumsq
__device__ float g_pool[NGRAPHS * HID];    // pooled graph features
// CSR by destination
__device__ int g_cnt[N_NODES];
__device__ int g_off[N_NODES + 1];
__device__ int g_cur[N_NODES];
__device__ int g_csr_src[N_EDGES];
// parallel scan scratch
#define NCHUNK 1024
#define CHSZ ((N_NODES + NCHUNK - 1) / NCHUNK)
__device__ int g_chunk[NCHUNK];
__device__ int g_chunk_base[NCHUNK];

// ---------------- f32x2 packed helpers ---------------------------------------
__device__ __forceinline__ u64 pk2(float x, float y) {
    u64 r; asm("mov.b64 %0,{%1,%2};" : "=l"(r) : "f"(x), "f"(y)); return r;
}
__device__ __forceinline__ void upk2(u64 v, float& x, float& y) {
    asm("mov.b64 {%0,%1},%2;" : "=f"(x), "=f"(y) : "l"(v));
}
__device__ __forceinline__ u64 fma2(u64 a, u64 b, u64 c) {
    u64 d; asm("fma.rn.f32x2 %0,%1,%2,%3;" : "=l"(d) : "l"(a), "l"(b), "l"(c)); return d;
}

__device__ __forceinline__ void red_add_v4(float* p, float4 v) {
    asm volatile("red.global.add.v4.f32 [%0], {%1,%2,%3,%4};"
                 :: "l"(p), "f"(v.x), "f"(v.y), "f"(v.z), "f"(v.w) : "memory");
}

__device__ __forceinline__ float4 h16_load4(const __half* p) {
    uint2 u = *reinterpret_cast<const uint2*>(p);
    __half2 a = *reinterpret_cast<__half2*>(&u.x);
    __half2 b = *reinterpret_cast<__half2*>(&u.y);
    float2 fa = __half22float2(a);
    float2 fb = __half22float2(b);
    return make_float4(fa.x, fa.y, fb.x, fb.y);
}
__device__ __forceinline__ void h16_store4(__half* p, float4 v) {
    union { __half2 h[2]; uint2 u; } cv;
    cv.h[0] = __floats2half2_rn(v.x, v.y);
    cv.h[1] = __floats2half2_rn(v.z, v.w);
    *reinterpret_cast<uint2*>(p) = cv.u;
}

// ---------------- node encoder: z16 = x @ node_w + node_b; also zeros -------
__global__ void encoder_kernel(const float* __restrict__ x,
                               const float* __restrict__ W,
                               const float* __restrict__ b) {
    int gt = blockIdx.x * blockDim.x + threadIdx.x;
    int gsz = gridDim.x * blockDim.x;
    for (int i = gt; i < N_NODES; i += gsz) g_cnt[i] = 0;
    for (int i = gt; i < NGRAPHS * HID; i += gsz) g_pool[i] = 0.f;
    for (int i = gt; i < NLAYERS * 2 * HID; i += gsz) g_stats[i] = 0.f;

    __shared__ float sW[NODE_DIM * HID];
    for (int i = threadIdx.x; i < NODE_DIM * HID; i += blockDim.x) sW[i] = W[i];
    __syncthreads();
    int lane = threadIdx.x & 31;
    int warp = gt >> 5;
    int nw = gsz >> 5;
    float4 bb = reinterpret_cast<const float4*>(b)[lane];
    for (int n = warp; n < N_NODES; n += nw) {
        const float4* xr = reinterpret_cast<const float4*>(x + (size_t)n * NODE_DIM);
        float4 acc = bb;
        #pragma unroll
        for (int kk = 0; kk < NODE_DIM / 4; kk++) {
            float4 xv = xr[kk];
            float xa[4] = {xv.x, xv.y, xv.z, xv.w};
            #pragma unroll
            for (int j = 0; j < 4; j++) {
                float4 w = *reinterpret_cast<const float4*>(&sW[(4 * kk + j) * HID + 4 * lane]);
                acc.x += xa[j] * w.x;
                acc.y += xa[j] * w.y;
                acc.z += xa[j] * w.z;
                acc.w += xa[j] * w.w;
            }
        }
        h16_store4(g_z16 + (size_t)n * HID + 4 * lane, acc);
    }
}

// ---------------- CSR build --------------------------------------------------
__global__ void csr_count_kernel(const int* __restrict__ eidx) {
    int e = blockIdx.x * blockDim.x + threadIdx.x;
    if (e < N_EDGES) atomicAdd(&g_cnt[eidx[N_EDGES + e]], 1);
}

__global__ void chunk_sum_kernel() {
    int t = blockIdx.x * blockDim.x + threadIdx.x;
    if (t >= NCHUNK) return;
    int beg = t * CHSZ;
    int end = min(beg + CHSZ, N_NODES);
    int s = 0;
    for (int i = beg; i < end; i++) s += g_cnt[i];
    g_chunk[t] = s;
}

__global__ void chunk_scan_kernel() {
    __shared__ int ssum[NCHUNK];
    int t = threadIdx.x;
    ssum[t] = g_chunk[t];
    __syncthreads();
    for (int off = 1; off < NCHUNK; off <<= 1) {
        int v = (t >= off) ? ssum[t - off] : 0;
        __syncthreads();
        ssum[t] += v;
        __syncthreads();
    }
    g_chunk_base[t] = (t == 0) ? 0 : ssum[t - 1];
    if (t == NCHUNK - 1) g_off[N_NODES] = ssum[t];
}

__global__ void chunk_offs_kernel() {
    int t = blockIdx.x * blockDim.x + threadIdx.x;
    if (t >= NCHUNK) return;
    int beg = t * CHSZ;
    int end = min(beg + CHSZ, N_NODES);
    int run = g_chunk_base[t];
    for (int i = beg; i < end; i++) {
        g_off[i] = run;
        g_cur[i] = run;
        run += g_cnt[i];
    }
}

// --- fused: csr_fill + edge encoder -> fp16 rows in CSR order ---------------
__global__ void edge_enc_fill_kernel(const float* __restrict__ eattr,
                                     const int* __restrict__ eidx,
                                     const float* __restrict__ W,
                                     const float* __restrict__ b) {
    __shared__ float sW[EDGE_DIM * HID];
    __shared__ float sb[HID];
    for (int i = threadIdx.x; i < EDGE_DIM * HID; i += blockDim.x) sW[i] = W[i];
    if (threadIdx.x < HID) sb[threadIdx.x] = b[threadIdx.x];
    __syncthreads();
    int lane = threadIdx.x & 31;
    int warp = (blockIdx.x * blockDim.x + threadIdx.x) >> 5;
    int nw = (gridDim.x * blockDim.x) >> 5;
    float4 bb = reinterpret_cast<const float4*>(sb)[lane];
    for (int e = warp; e < N_EDGES; e += nw) {
        int slot = 0;
        if (lane == 0) {
            int src = eidx[e];
            int dst = eidx[N_EDGES + e];
            slot = atomicAdd(&g_cur[dst], 1);
            g_csr_src[slot] = src;
        }
        slot = __shfl_sync(0xffffffffu, slot, 0);
        const float4* ar = reinterpret_cast<const float4*>(eattr + (size_t)e * EDGE_DIM);
        float4 acc = bb;
        #pragma unroll
        for (int kk = 0; kk < EDGE_DIM / 4; kk++) {
            float4 av = ar[kk];
            float xa[4] = {av.x, av.y, av.z, av.w};
            #pragma unroll
            for (int j = 0; j < 4; j++) {
                float4 w = *reinterpret_cast<const float4*>(&sW[(4 * kk + j) * HID + 4 * lane]);
                acc.x += xa[j] * w.x;
                acc.y += xa[j] * w.y;
                acc.z += xa[j] * w.z;
                acc.w += xa[j] * w.w;
            }
        }
        h16_store4(g_ea_h + (size_t)slot * HID + 4 * lane, acc);
    }
}

// ---- aggregation with inline BN of previous layer, edge loop unrolled x4 ----
template<bool BN>
__global__ void agg_kernel(const float* __restrict__ gamma,
                           const float* __restrict__ beta,
                           const float* __restrict__ stats) {
    __shared__ float s_sc[HID], s_sh[HID];
    if (BN) {
        if (threadIdx.x < HID) {
            int c = threadIdx.x;
            const float invN = 1.0f / (float)N_NODES;
            float mean = stats[c] * invN;
            float var = stats[HID + c] * invN - mean * mean;
            float rstd = rsqrtf(var + BN_EPS);
            float sc = gamma[c] * rstd;
            s_sc[c] = sc;
            s_sh[c] = beta[c] - sc * mean;
        }
        __syncthreads();
    }
    int lane = threadIdx.x & 31;
    int warp = (blockIdx.x * blockDim.x + threadIdx.x) >> 5;
    int nw = (gridDim.x * blockDim.x) >> 5;
    float4 sc4 = make_float4(1.f, 1.f, 1.f, 1.f), sh4 = make_float4(0.f, 0.f, 0.f, 0.f);
    if (BN) {
        sc4 = *reinterpret_cast<const float4*>(&s_sc[4 * lane]);
        sh4 = *reinterpret_cast<const float4*>(&s_sh[4 * lane]);
    }

    const __half* zp = g_z16;
    const __half* ep = g_ea_h;

    for (int n = warp; n < N_NODES; n += nw) {
        float4 z = h16_load4(zp + (size_t)n * HID + 4 * lane);
        float4 acc;
        if (BN) {
            acc.x = fmaxf(fmaf(z.x, sc4.x, sh4.x), 0.f);
            acc.y = fmaxf(fmaf(z.y, sc4.y, sh4.y), 0.f);
            acc.z = fmaxf(fmaf(z.z, sc4.z, sh4.z), 0.f);
            acc.w = fmaxf(fmaf(z.w, sc4.w, sh4.w), 0.f);
        } else {
            acc = z;
        }
        int s = __ldg(&g_off[n]);
        int e = __ldg(&g_off[n + 1]);
        int idx = s;
        // main unrolled-by-4 loop: 4 independent gathers in flight
        for (; idx + 4 <= e; idx += 4) {
            int s0 = __ldg(&g_csr_src[idx]);
            int s1 = __ldg(&g_csr_src[idx + 1]);
            int s2 = __ldg(&g_csr_src[idx + 2]);
            int s3 = __ldg(&g_csr_src[idx + 3]);
            float4 h0 = h16_load4(zp + (size_t)s0 * HID + 4 * lane);
            float4 h1 = h16_load4(zp + (size_t)s1 * HID + 4 * lane);
            float4 h2 = h16_load4(zp + (size_t)s2 * HID + 4 * lane);
            float4 h3 = h16_load4(zp + (size_t)s3 * HID + 4 * lane);
            float4 e0 = h16_load4(ep + (size_t)(idx + 0) * HID + 4 * lane);
            float4 e1 = h16_load4(ep + (size_t)(idx + 1) * HID + 4 * lane);
            float4 e2 = h16_load4(ep + (size_t)(idx + 2) * HID + 4 * lane);
            float4 e3 = h16_load4(ep + (size_t)(idx + 3) * HID + 4 * lane);
            if (BN) {
                h0.x = fmaxf(fmaf(h0.x, sc4.x, sh4.x), 0.f); h0.y = fmaxf(fmaf(h0.y, sc4.y, sh4.y), 0.f);
                h0.z = fmaxf(fmaf(h0.z, sc4.z, sh4.z), 0.f); h0.w = fmaxf(fmaf(h0.w, sc4.w, sh4.w), 0.f);
                h1.x = fmaxf(fmaf(h1.x, sc4.x, sh4.x), 0.f); h1.y = fmaxf(fmaf(h1.y, sc4.y, sh4.y), 0.f);
                h1.z = fmaxf(fmaf(h1.z, sc4.z, sh4.z), 0.f); h1.w = fmaxf(fmaf(h1.w, sc4.w, sh4.w), 0.f);
                h2.x = fmaxf(fmaf(h2.x, sc4.x, sh4.x), 0.f); h2.y = fmaxf(fmaf(h2.y, sc4.y, sh4.y), 0.f);
                h2.z = fmaxf(fmaf(h2.z, sc4.z, sh4.z), 0.f); h2.w = fmaxf(fmaf(h2.w, sc4.w, sh4.w), 0.f);
                h3.x = fmaxf(fmaf(h3.x, sc4.x, sh4.x), 0.f); h3.y = fmaxf(fmaf(h3.y, sc4.y, sh4.y), 0.f);
                h3.z = fmaxf(fmaf(h3.z, sc4.z, sh4.z), 0.f); h3.w = fmaxf(fmaf(h3.w, sc4.w, sh4.w), 0.f);
            }
            acc.x += fmaxf(h0.x + e0.x, 0.f) + fmaxf(h1.x + e1.x, 0.f)
                   + fmaxf(h2.x + e2.x, 0.f) + fmaxf(h3.x + e3.x, 0.f);
            acc.y += fmaxf(h0.y + e0.y, 0.f) + fmaxf(h1.y + e1.y, 0.f)
                   + fmaxf(h2.y + e2.y, 0.f) + fmaxf(h3.y + e3.y, 0.f);
            acc.z += fmaxf(h0.z + e0.z, 0.f) + fmaxf(h1.z + e1.z, 0.f)
                   + fmaxf(h2.z + e2.z, 0.f) + fmaxf(h3.z + e3.z, 0.f);
            acc.w += fmaxf(h0.w + e0.w, 0.f) + fmaxf(h1.w + e1.w, 0.f)
                   + fmaxf(h2.w + e2.w, 0.f) + fmaxf(h3.w + e3.w, 0.f);
        }
        for (; idx < e; idx++) {
            int src = __ldg(&g_csr_src[idx]);
            float4 hv = h16_load4(zp + (size_t)src * HID + 4 * lane);
            float4 ev = h16_load4(ep + (size_t)idx * HID + 4 * lane);
            if (BN) {
                hv.x = fmaxf(fmaf(hv.x, sc4.x, sh4.x), 0.f);
                hv.y = fmaxf(fmaf(hv.y, sc4.y, sh4.y), 0.f);
                hv.z = fmaxf(fmaf(hv.z, sc4.z, sh4.z), 0.f);
                hv.w = fmaxf(fmaf(hv.w, sc4.w, sh4.w), 0.f);
            }
            acc.x += fmaxf(hv.x + ev.x, 0.f);
            acc.y += fmaxf(hv.y + ev.y, 0.f);
            acc.z += fmaxf(hv.z + ev.z, 0.f);
            acc.w += fmaxf(hv.w + ev.w, 0.f);
        }
        h16_store4(g_zin16 + (size_t)n * HID + 4 * lane, acc);
    }
}

// ---------------- per-layer MLP: z16 = relu(zin@W1+b1)@W2+b2, + BN stats ----
#define TSTR 129
#define MLP_THREADS 512
#define MLP_SMEM_FLOATS (2 * HID * HID + HID * TSTR + 2 * HID)
__global__ __launch_bounds__(MLP_THREADS, 1)
void mlp_kernel(const float* __restrict__ W1, const float* __restrict__ B1,
                const float* __restrict__ W2, const float* __restrict__ B2,
                float* __restrict__ stats) {
    extern __shared__ float sm[];
    float* sW1 = sm;
    float* sW2 = sm + HID * HID;
    float* sT  = sm + 2 * HID * HID;          // 128 x 129 padded tile
    float* sB1 = sT + HID * TSTR;
    float* sB2 = sB1 + HID;

    int tid = threadIdx.x;
    int lane = tid & 31;
    int wid = tid >> 5;
    for (int i = tid; i < HID * HID; i += MLP_THREADS) { sW1[i] = W1[i]; sW2[i] = W2[i]; }
    if (tid < HID) { sB1[tid] = B1[tid]; sB2[tid] = B2[tid]; }
    __syncthreads();

    const int c0 = wid * 8;

    u64 bb1[4], bb2[4];
    #pragma unroll
    for (int j = 0; j < 4; j++) {
        bb1[j] = pk2(sB1[c0 + 2 * j], sB1[c0 + 2 * j + 1]);
        bb2[j] = pk2(sB2[c0 + 2 * j], sB2[c0 + 2 * j + 1]);
    }

    int rpb = (N_NODES + gridDim.x - 1) / gridDim.x;
    int base = blockIdx.x * rpb;
    int rend = min(base + rpb, N_NODES);

    float ls[8], lss[8];
    #pragma unroll
    for (int j = 0; j < 8; j++) { ls[j] = 0.f; lss[j] = 0.f; }

    for (int rbase = base; rbase < rend; rbase += HID) {
        // load fp16 input tile into padded smem (8 halves per iteration)
        for (int i = tid; i < HID * 16; i += MLP_THREADS) {
            int r = i >> 4;
            int q = i & 15;
            int row = rbase + r;
            float f[8];
            if (row < rend) {
                uint4 u = *reinterpret_cast<const uint4*>(g_zin16 + (size_t)row * HID + q * 8);
                float2 a = __half22float2(*reinterpret_cast<__half2*>(&u.x));
                float2 b = __half22float2(*reinterpret_cast<__half2*>(&u.y));
                float2 c = __half22float2(*reinterpret_cast<__half2*>(&u.z));
                float2 d = __half22float2(*reinterpret_cast<__half2*>(&u.w));
                f[0] = a.x; f[1] = a.y; f[2] = b.x; f[3] = b.y;
                f[4] = c.x; f[5] = c.y; f[6] = d.x; f[7] = d.y;
            } else {
                #pragma unroll
                for (int j = 0; j < 8; j++) f[j] = 0.f;
            }
            float* dst = &sT[r * TSTR + q * 8];
            #pragma unroll
            for (int j = 0; j < 8; j++) dst[j] = f[j];
        }
        __syncthreads();

        // stage 1: T = relu(In @ W1 + b1)
        u64 acc[4][4];
        #pragma unroll
        for (int i = 0; i < 4; i++)
            #pragma unroll
            for (int j = 0; j < 4; j++) acc[i][j] = bb1[j];
        #pragma unroll 4
        for (int k = 0; k < HID; k++) {
            float4 wa = *reinterpret_cast<const float4*>(&sW1[k * HID + c0]);
            float4 wb = *reinterpret_cast<const float4*>(&sW1[k * HID + c0 + 4]);
            u64 w0 = pk2(wa.x, wa.y), w1 = pk2(wa.z, wa.w);
            u64 w2 = pk2(wb.x, wb.y), w3 = pk2(wb.z, wb.w);
            #pragma unroll
            for (int i = 0; i < 4; i++) {
                float a = sT[(lane + 32 * i) * TSTR + k];
                u64 a2 = pk2(a, a);
                acc[i][0] = fma2(a2, w0, acc[i][0]);
                acc[i][1] = fma2(a2, w1, acc[i][1]);
                acc[i][2] = fma2(a2, w2, acc[i][2]);
                acc[i][3] = fma2(a2, w3, acc[i][3]);
            }
        }
        float t[4][8];
        #pragma unroll
        for (int i = 0; i < 4; i++)
            #pragma unroll
            for (int j = 0; j < 4; j++) {
                float v0, v1;
                upk2(acc[i][j], v0, v1);
                t[i][2 * j] = fmaxf(v0, 0.f);
                t[i][2 * j + 1] = fmaxf(v1, 0.f);
            }
        __syncthreads();
        #pragma unroll
        for (int i = 0; i < 4; i++) {
            float* dst = &sT[(lane + 32 * i) * TSTR + c0];
            #pragma unroll
            for (int j = 0; j < 8; j++) dst[j] = t[i][j];
        }
        __syncthreads();

        // stage 2: z = T @ W2 + b2
        #pragma unroll
        for (int i = 0; i < 4; i++)
            #pragma unroll
            for (int j = 0; j < 4; j++) acc[i][j] = bb2[j];
        #pragma unroll 4
        for (int k = 0; k < HID; k++) {
            float4 wa = *reinterpret_cast<const float4*>(&sW2[k * HID + c0]);
            float4 wb = *reinterpret_cast<const float4*>(&sW2[k * HID + c0 + 4]);
            u64 w0 = pk2(wa.x, wa.y), w1 = pk2(wa.z, wa.w);
            u64 w2 = pk2(wb.x, wb.y), w3 = pk2(wb.z, wb.w);
            #pragma unroll
            for (int i = 0; i < 4; i++) {
                float a = sT[(lane + 32 * i) * TSTR + k];
                u64 a2 = pk2(a, a);
                acc[i][0] = fma2(a2, w0, acc[i][0]);
                acc[i][1] = fma2(a2, w1, acc[i][1]);
                acc[i][2] = fma2(a2, w2, acc[i][2]);
                acc[i][3] = fma2(a2, w3, acc[i][3]);
            }
        }
        #pragma unroll
        for (int i = 0; i < 4; i++) {
            int row = rbase + lane + 32 * i;
            if (row < rend) {
                float z[8];
                #pragma unroll
                for (int j = 0; j < 4; j++) upk2(acc[i][j], z[2 * j], z[2 * j + 1]);
                union { __half2 h[4]; uint4 u; } cv;
                cv.h[0] = __floats2half2_rn(z[0], z[1]);
                cv.h[1] = __floats2half2_rn(z[2], z[3]);
                cv.h[2] = __floats2half2_rn(z[4], z[5]);
                cv.h[3] = __floats2half2_rn(z[6], z[7]);
                *reinterpret_cast<uint4*>(g_z16 + (size_t)row * HID + c0) = cv.u;
                #pragma unroll
                for (int j = 0; j < 8; j++) {
                    ls[j] += z[j];
                    lss[j] += z[j] * z[j];
                }
            }
        }
        __syncthreads();
    }

    // warp-reduce stats across lanes (cols warp-uniform), lane0 atomics
    #pragma unroll
    for (int j = 0; j < 8; j++) {
        #pragma unroll
        for (int o = 16; o > 0; o >>= 1) {
            ls[j]  += __shfl_down_sync(0xffffffffu, ls[j], o);
            lss[j] += __shfl_down_sync(0xffffffffu, lss[j], o);
        }
    }
    if (lane == 0) {
        #pragma unroll
        for (int j = 0; j < 8; j++) {
            atomicAdd(&stats[c0 + j], ls[j]);
            atomicAdd(&stats[HID + c0 + j], lss[j]);
        }
    }
}

// ---------------- last layer: BN + relu + pool (reads z16) ------------------
__global__ void bn_pool_kernel(const float* __restrict__ gamma,
                               const float* __restrict__ beta,
                               const float* __restrict__ stats,
                               const int* __restrict__ batch) {
    int i = blockIdx.x * blockDim.x + threadIdx.x;  // float4-group index
    const int n4 = N_NODES * HID / 4;
    if (i >= n4) return;
    int n = i >> 5;
    int c0 = (i & 31) * 4;
    float4 z = h16_load4(g_z16 + (size_t)i * 4);
    float za[4] = {z.x, z.y, z.z, z.w};
    float out[4];
    const float invN = 1.0f / (float)N_NODES;
    #pragma unroll
    for (int j = 0; j < 4; j++) {
        int c = c0 + j;
        float mean = stats[c] * invN;
        float var = stats[HID + c] * invN - mean * mean;
        float rstd = rsqrtf(var + BN_EPS);
        float o = gamma[c] * (za[j] - mean) * rstd + beta[c];
        out[j] = fmaxf(o, 0.f);
    }
    int gi = __ldg(&batch[n]);
    red_add_v4(g_pool + (size_t)gi * HID + c0,
               make_float4(out[0], out[1], out[2], out[3]));
}

// ---------------- head: out = relu(g@W1+b1)@W2+b2 ---------------------------
__global__ void head_kernel(const float* __restrict__ w1, const float* __restrict__ b1,
                            const float* __restrict__ w2, const float* __restrict__ b2,
                            float* __restrict__ out) {
    __shared__ float srow[HID];
    __shared__ float st[HID];
    int gi = blockIdx.x;
    int c = threadIdx.x;
    srow[c] = g_pool[(size_t)gi * HID + c];
    __syncthreads();
    float acc = b1[c];
    for (int k = 0; k < HID; k++) acc += srow[k] * w1[k * HID + c];
    st[c] = fmaxf(acc, 0.f);
    __syncthreads();
    if (c < 2) {
        float o = b2[c];
        for (int k = 0; k < HID; k++) o += st[k] * w2[k * 2 + c];
        out[gi * 2 + c] = o;
    }
}

// ---------------- launch -----------------------------------------------------
extern "C" void kernel_launch(void* const* d_in, const int* in_sizes, int n_in,
                              void* d_out, int out_size) {
    const float* x        = (const float*)d_in[0];
    const int*   eidx     = (const int*)d_in[1];
    const float* eattr    = (const float*)d_in[2];
    const int*   batch    = (const int*)d_in[3];
    const float* node_w   = (const float*)d_in[4];
    const float* node_b   = (const float*)d_in[5];
    const float* edge_w   = (const float*)d_in[6];
    const float* edge_b   = (const float*)d_in[7];
    const float* mlp_w1   = (const float*)d_in[8];
    const float* mlp_b1   = (const float*)d_in[9];
    const float* mlp_w2   = (const float*)d_in[10];
    const float* mlp_b2   = (const float*)d_in[11];
    const float* bn_gamma = (const float*)d_in[12];
    const float* bn_beta  = (const float*)d_in[13];
    const float* head_w1  = (const float*)d_in[14];
    const float* head_b1  = (const float*)d_in[15];
    const float* head_w2  = (const float*)d_in[16];
    const float* head_b2  = (const float*)d_in[17];
    float* out = (float*)d_out;

    const int mlp_smem = MLP_SMEM_FLOATS * (int)sizeof(float);
    cudaFuncSetAttribute(mlp_kernel, cudaFuncAttributeMaxDynamicSharedMemorySize, mlp_smem);

    float* d_stats;
    cudaGetSymbolAddress((void**)&d_stats, g_stats);

    // encoder (also zeros cnt/pool/stats) -> z16
    encoder_kernel<<<512, 256>>>(x, node_w, node_b);

    // CSR build (parallel scan), then fused fill + edge encoder
    csr_count_kernel<<<(N_EDGES + 255) / 256, 256>>>(eidx);
    chunk_sum_kernel<<<NCHUNK / 128, 128>>>();
    chunk_scan_kernel<<<1, NCHUNK>>>();
    chunk_offs_kernel<<<NCHUNK / 128, 128>>>();
    edge_enc_fill_kernel<<<2048, 256>>>(eattr, eidx, edge_w, edge_b);

    for (int l = 0; l < NLAYERS; l++) {
        if (l == 0) {
            agg_kernel<false><<<2048, 256>>>(nullptr, nullptr, nullptr);
        } else {
            agg_kernel<true><<<2048, 256>>>(bn_gamma + (size_t)(l - 1) * HID,
                                            bn_beta + (size_t)(l - 1) * HID,
                                            d_stats + (size_t)(l - 1) * 2 * HID);
        }
        mlp_kernel<<<148, MLP_THREADS, mlp_smem>>>(mlp_w1 + (size_t)l * HID * HID,
                                                   mlp_b1 + (size_t)l * HID,
                                                   mlp_w2 + (size_t)l * HID * HID,
                                                   mlp_b2 + (size_t)l * HID,
                                                   d_stats + (size_t)l * 2 * HID);
    }

    bn_pool_kernel<<<(N_NODES * HID / 4 + 255) / 256, 256>>>(
        bn_gamma + (size_t)(NLAYERS - 1) * HID,
        bn_beta + (size_t)(NLAYERS - 1) * HID,
        d_stats + (size_t)(NLAYERS - 1) * 2 * HID, batch);
    head_kernel<<<NGRAPHS, HID>>>(head_w1, head_b1, head_w2, head_b2, out);
}

// round 10
// speedup vs baseline: 1.6897x; 1.2604x over previous
#include <cuda_runtime.h>
#include <cuda_fp16.h>

#define N_NODES 50000
#define N_EDGES 600000
#define HID 128
#define NODE_DIM 64
#define EDGE_DIM 16
#define NLAYERS 3
#define NGRAPHS 256
#define BN_EPS 1e-5f

typedef unsigned long long u64;

// ---------------- scratch (device globals; no allocations allowed) ----------
__device__ __half g_z16[N_NODES * HID];    // node features / pre-BN z, fp16
__device__ __half g_zin16[N_NODES * HID];  // h + agg (MLP input), fp16
__device__ __half g_ea_h[N_EDGES * HID];   // encoded edge features, fp16, CSR order
__device__ __half g_w16[NLAYERS * 2 * HID * HID];  // fp16 MLP weights
__device__ float g_stats[NLAYERS * 2 * HID]; // per-layer column sums / sumsq
__device__ float g_pool[NGRAPHS * HID];    // pooled graph features
// CSR by destination
__device__ int g_cnt[N_NODES];
__device__ int g_off[N_NODES + 1];
__device__ int g_cur[N_NODES];
__device__ int g_csr_src[N_EDGES];
// parallel scan scratch
#define NCHUNK 1024
#define CHSZ ((N_NODES + NCHUNK - 1) / NCHUNK)
__device__ int g_chunk[NCHUNK];
__device__ int g_chunk_base[NCHUNK];

// ---------------- helpers ----------------------------------------------------
__device__ __forceinline__ void red_add_v4(float* p, float4 v) {
    asm volatile("red.global.add.v4.f32 [%0], {%1,%2,%3,%4};"
                 :: "l"(p), "f"(v.x), "f"(v.y), "f"(v.z), "f"(v.w) : "memory");
}

__device__ __forceinline__ float4 h16_load4(const __half* p) {
    uint2 u = *reinterpret_cast<const uint2*>(p);
    __half2 a = *reinterpret_cast<__half2*>(&u.x);
    __half2 b = *reinterpret_cast<__half2*>(&u.y);
    float2 fa = __half22float2(a);
    float2 fb = __half22float2(b);
    return make_float4(fa.x, fa.y, fb.x, fb.y);
}
__device__ __forceinline__ void h16_store4(__half* p, float4 v) {
    union { __half2 h[2]; uint2 u; } cv;
    cv.h[0] = __floats2half2_rn(v.x, v.y);
    cv.h[1] = __floats2half2_rn(v.z, v.w);
    *reinterpret_cast<uint2*>(p) = cv.u;
}

__device__ __forceinline__ unsigned smem_u32(const void* p) {
    return (unsigned)__cvta_generic_to_shared(p);
}
__device__ __forceinline__ void ldsm_x4(unsigned addr, unsigned& r0, unsigned& r1,
                                        unsigned& r2, unsigned& r3) {
    asm volatile("ldmatrix.sync.aligned.m8n8.x4.shared.b16 {%0,%1,%2,%3},[%4];"
                 : "=r"(r0), "=r"(r1), "=r"(r2), "=r"(r3) : "r"(addr));
}
__device__ __forceinline__ void ldsm_x4_t(unsigned addr, unsigned& r0, unsigned& r1,
                                          unsigned& r2, unsigned& r3) {
    asm volatile("ldmatrix.sync.aligned.m8n8.x4.trans.shared.b16 {%0,%1,%2,%3},[%4];"
                 : "=r"(r0), "=r"(r1), "=r"(r2), "=r"(r3) : "r"(addr));
}
__device__ __forceinline__ void mma16816(float& c0, float& c1, float& c2, float& c3,
                                         unsigned a0, unsigned a1, unsigned a2, unsigned a3,
                                         unsigned b0, unsigned b1) {
    asm volatile("mma.sync.aligned.m16n8k16.row.col.f32.f16.f16.f32 "
                 "{%0,%1,%2,%3},{%4,%5,%6,%7},{%8,%9},{%0,%1,%2,%3};"
                 : "+f"(c0), "+f"(c1), "+f"(c2), "+f"(c3)
                 : "r"(a0), "r"(a1), "r"(a2), "r"(a3), "r"(b0), "r"(b1));
}

// ---------------- weight conversion (once) ----------------------------------
__global__ void convert_w_kernel(const float* __restrict__ w1,
                                 const float* __restrict__ w2) {
    int i = blockIdx.x * blockDim.x + threadIdx.x;
    const int per = NLAYERS * HID * HID;
    if (i < per) {
        int l = i / (HID * HID);
        int j = i % (HID * HID);
        g_w16[(size_t)l * 2 * HID * HID + j] = __float2half(w1[i]);
    } else if (i < 2 * per) {
        int k = i - per;
        int l = k / (HID * HID);
        int j = k % (HID * HID);
        g_w16[(size_t)l * 2 * HID * HID + HID * HID + j] = __float2half(w2[k]);
    }
}

// ---------------- node encoder: z16 = x @ node_w + node_b; also zeros -------
__global__ void encoder_kernel(const float* __restrict__ x,
                               const float* __restrict__ W,
                               const float* __restrict__ b) {
    int gt = blockIdx.x * blockDim.x + threadIdx.x;
    int gsz = gridDim.x * blockDim.x;
    for (int i = gt; i < N_NODES; i += gsz) g_cnt[i] = 0;
    for (int i = gt; i < NGRAPHS * HID; i += gsz) g_pool[i] = 0.f;
    for (int i = gt; i < NLAYERS * 2 * HID; i += gsz) g_stats[i] = 0.f;

    __shared__ float sW[NODE_DIM * HID];
    for (int i = threadIdx.x; i < NODE_DIM * HID; i += blockDim.x) sW[i] = W[i];
    __syncthreads();
    int lane = threadIdx.x & 31;
    int warp = gt >> 5;
    int nw = gsz >> 5;
    float4 bb = reinterpret_cast<const float4*>(b)[lane];
    for (int n = warp; n < N_NODES; n += nw) {
        const float4* xr = reinterpret_cast<const float4*>(x + (size_t)n * NODE_DIM);
        float4 acc = bb;
        #pragma unroll
        for (int kk = 0; kk < NODE_DIM / 4; kk++) {
            float4 xv = xr[kk];
            float xa[4] = {xv.x, xv.y, xv.z, xv.w};
            #pragma unroll
            for (int j = 0; j < 4; j++) {
                float4 w = *reinterpret_cast<const float4*>(&sW[(4 * kk + j) * HID + 4 * lane]);
                acc.x += xa[j] * w.x;
                acc.y += xa[j] * w.y;
                acc.z += xa[j] * w.z;
                acc.w += xa[j] * w.w;
            }
        }
        h16_store4(g_z16 + (size_t)n * HID + 4 * lane, acc);
    }
}

// ---------------- CSR build --------------------------------------------------
__global__ void csr_count_kernel(const int* __restrict__ eidx) {
    int e = blockIdx.x * blockDim.x + threadIdx.x;
    if (e < N_EDGES) atomicAdd(&g_cnt[eidx[N_EDGES + e]], 1);
}

__global__ void chunk_sum_kernel() {
    int t = blockIdx.x * blockDim.x + threadIdx.x;
    if (t >= NCHUNK) return;
    int beg = t * CHSZ;
    int end = min(beg + CHSZ, N_NODES);
    int s = 0;
    for (int i = beg; i < end; i++) s += g_cnt[i];
    g_chunk[t] = s;
}

__global__ void chunk_scan_kernel() {
    __shared__ int ssum[NCHUNK];
    int t = threadIdx.x;
    ssum[t] = g_chunk[t];
    __syncthreads();
    for (int off = 1; off < NCHUNK; off <<= 1) {
        int v = (t >= off) ? ssum[t - off] : 0;
        __syncthreads();
        ssum[t] += v;
        __syncthreads();
    }
    g_chunk_base[t] = (t == 0) ? 0 : ssum[t - 1];
    if (t == NCHUNK - 1) g_off[N_NODES] = ssum[t];
}

__global__ void chunk_offs_kernel() {
    int t = blockIdx.x * blockDim.x + threadIdx.x;
    if (t >= NCHUNK) return;
    int beg = t * CHSZ;
    int end = min(beg + CHSZ, N_NODES);
    int run = g_chunk_base[t];
    for (int i = beg; i < end; i++) {
        g_off[i] = run;
        g_cur[i] = run;
        run += g_cnt[i];
    }
}

// --- fused: csr_fill + edge encoder -> fp16 rows in CSR order ---------------
__global__ void edge_enc_fill_kernel(const float* __restrict__ eattr,
                                     const int* __restrict__ eidx,
                                     const float* __restrict__ W,
                                     const float* __restrict__ b) {
    __shared__ float sW[EDGE_DIM * HID];
    __shared__ float sb[HID];
    for (int i = threadIdx.x; i < EDGE_DIM * HID; i += blockDim.x) sW[i] = W[i];
    if (threadIdx.x < HID) sb[threadIdx.x] = b[threadIdx.x];
    __syncthreads();
    int lane = threadIdx.x & 31;
    int warp = (blockIdx.x * blockDim.x + threadIdx.x) >> 5;
    int nw = (gridDim.x * blockDim.x) >> 5;
    float4 bb = reinterpret_cast<const float4*>(sb)[lane];
    for (int e = warp; e < N_EDGES; e += nw) {
        int slot = 0;
        if (lane == 0) {
            int src = eidx[e];
            int dst = eidx[N_EDGES + e];
            slot = atomicAdd(&g_cur[dst], 1);
            g_csr_src[slot] = src;
        }
        slot = __shfl_sync(0xffffffffu, slot, 0);
        const float4* ar = reinterpret_cast<const float4*>(eattr + (size_t)e * EDGE_DIM);
        float4 acc = bb;
        #pragma unroll
        for (int kk = 0; kk < EDGE_DIM / 4; kk++) {
            float4 av = ar[kk];
            float xa[4] = {av.x, av.y, av.z, av.w};
            #pragma unroll
            for (int j = 0; j < 4; j++) {
                float4 w = *reinterpret_cast<const float4*>(&sW[(4 * kk + j) * HID + 4 * lane]);
                acc.x += xa[j] * w.x;
                acc.y += xa[j] * w.y;
                acc.z += xa[j] * w.z;
                acc.w += xa[j] * w.w;
            }
        }
        h16_store4(g_ea_h + (size_t)slot * HID + 4 * lane, acc);
    }
}

// ---- aggregation with inline BN of previous layer, edge loop unrolled x4 ----
template<bool BN>
__global__ void agg_kernel(const float* __restrict__ gamma,
                           const float* __restrict__ beta,
                           const float* __restrict__ stats) {
    __shared__ float s_sc[HID], s_sh[HID];
    if (BN) {
        if (threadIdx.x < HID) {
            int c = threadIdx.x;
            const float invN = 1.0f / (float)N_NODES;
            float mean = stats[c] * invN;
            float var = stats[HID + c] * invN - mean * mean;
            float rstd = rsqrtf(var + BN_EPS);
            float sc = gamma[c] * rstd;
            s_sc[c] = sc;
            s_sh[c] = beta[c] - sc * mean;
        }
        __syncthreads();
    }
    int lane = threadIdx.x & 31;
    int warp = (blockIdx.x * blockDim.x + threadIdx.x) >> 5;
    int nw = (gridDim.x * blockDim.x) >> 5;
    float4 sc4 = make_float4(1.f, 1.f, 1.f, 1.f), sh4 = make_float4(0.f, 0.f, 0.f, 0.f);
    if (BN) {
        sc4 = *reinterpret_cast<const float4*>(&s_sc[4 * lane]);
        sh4 = *reinterpret_cast<const float4*>(&s_sh[4 * lane]);
    }

    const __half* zp = g_z16;
    const __half* ep = g_ea_h;

    for (int n = warp; n < N_NODES; n += nw) {
        float4 z = h16_load4(zp + (size_t)n * HID + 4 * lane);
        float4 acc;
        if (BN) {
            acc.x = fmaxf(fmaf(z.x, sc4.x, sh4.x), 0.f);
            acc.y = fmaxf(fmaf(z.y, sc4.y, sh4.y), 0.f);
            acc.z = fmaxf(fmaf(z.z, sc4.z, sh4.z), 0.f);
            acc.w = fmaxf(fmaf(z.w, sc4.w, sh4.w), 0.f);
        } else {
            acc = z;
        }
        int s = __ldg(&g_off[n]);
        int e = __ldg(&g_off[n + 1]);
        int idx = s;
        for (; idx + 4 <= e; idx += 4) {
            int s0 = __ldg(&g_csr_src[idx]);
            int s1 = __ldg(&g_csr_src[idx + 1]);
            int s2 = __ldg(&g_csr_src[idx + 2]);
            int s3 = __ldg(&g_csr_src[idx + 3]);
            float4 h0 = h16_load4(zp + (size_t)s0 * HID + 4 * lane);
            float4 h1 = h16_load4(zp + (size_t)s1 * HID + 4 * lane);
            float4 h2 = h16_load4(zp + (size_t)s2 * HID + 4 * lane);
            float4 h3 = h16_load4(zp + (size_t)s3 * HID + 4 * lane);
            float4 e0 = h16_load4(ep + (size_t)(idx + 0) * HID + 4 * lane);
            float4 e1 = h16_load4(ep + (size_t)(idx + 1) * HID + 4 * lane);
            float4 e2 = h16_load4(ep + (size_t)(idx + 2) * HID + 4 * lane);
            float4 e3 = h16_load4(ep + (size_t)(idx + 3) * HID + 4 * lane);
            if (BN) {
                h0.x = fmaxf(fmaf(h0.x, sc4.x, sh4.x), 0.f); h0.y = fmaxf(fmaf(h0.y, sc4.y, sh4.y), 0.f);
                h0.z = fmaxf(fmaf(h0.z, sc4.z, sh4.z), 0.f); h0.w = fmaxf(fmaf(h0.w, sc4.w, sh4.w), 0.f);
                h1.x = fmaxf(fmaf(h1.x, sc4.x, sh4.x), 0.f); h1.y = fmaxf(fmaf(h1.y, sc4.y, sh4.y), 0.f);
                h1.z = fmaxf(fmaf(h1.z, sc4.z, sh4.z), 0.f); h1.w = fmaxf(fmaf(h1.w, sc4.w, sh4.w), 0.f);
                h2.x = fmaxf(fmaf(h2.x, sc4.x, sh4.x), 0.f); h2.y = fmaxf(fmaf(h2.y, sc4.y, sh4.y), 0.f);
                h2.z = fmaxf(fmaf(h2.z, sc4.z, sh4.z), 0.f); h2.w = fmaxf(fmaf(h2.w, sc4.w, sh4.w), 0.f);
                h3.x = fmaxf(fmaf(h3.x, sc4.x, sh4.x), 0.f); h3.y = fmaxf(fmaf(h3.y, sc4.y, sh4.y), 0.f);
                h3.z = fmaxf(fmaf(h3.z, sc4.z, sh4.z), 0.f); h3.w = fmaxf(fmaf(h3.w, sc4.w, sh4.w), 0.f);
            }
            acc.x += fmaxf(h0.x + e0.x, 0.f) + fmaxf(h1.x + e1.x, 0.f)
                   + fmaxf(h2.x + e2.x, 0.f) + fmaxf(h3.x + e3.x, 0.f);
            acc.y += fmaxf(h0.y + e0.y, 0.f) + fmaxf(h1.y + e1.y, 0.f)
                   + fmaxf(h2.y + e2.y, 0.f) + fmaxf(h3.y + e3.y, 0.f);
            acc.z += fmaxf(h0.z + e0.z, 0.f) + fmaxf(h1.z + e1.z, 0.f)
                   + fmaxf(h2.z + e2.z, 0.f) + fmaxf(h3.z + e3.z, 0.f);
            acc.w += fmaxf(h0.w + e0.w, 0.f) + fmaxf(h1.w + e1.w, 0.f)
                   + fmaxf(h2.w + e2.w, 0.f) + fmaxf(h3.w + e3.w, 0.f);
        }
        for (; idx < e; idx++) {
            int src = __ldg(&g_csr_src[idx]);
            float4 hv = h16_load4(zp + (size_t)src * HID + 4 * lane);
            float4 ev = h16_load4(ep + (size_t)idx * HID + 4 * lane);
            if (BN) {
                hv.x = fmaxf(fmaf(hv.x, sc4.x, sh4.x), 0.f);
                hv.y = fmaxf(fmaf(hv.y, sc4.y, sh4.y), 0.f);
                hv.z = fmaxf(fmaf(hv.z, sc4.z, sh4.z), 0.f);
                hv.w = fmaxf(fmaf(hv.w, sc4.w, sh4.w), 0.f);
            }
            acc.x += fmaxf(hv.x + ev.x, 0.f);
            acc.y += fmaxf(hv.y + ev.y, 0.f);
            acc.z += fmaxf(hv.z + ev.z, 0.f);
            acc.w += fmaxf(hv.w + ev.w, 0.f);
        }
        h16_store4(g_zin16 + (size_t)n * HID + 4 * lane, acc);
    }
}

// ---------------- MLP via tensor cores (mma.sync m16n8k16) ------------------
// 512 thr = 4x4 warps, each warp = 32x32 of the 128x128 tile.
// smem halves, stride 136 (conflict-free ldmatrix).
#define LDT 136
#define MLP_SMEM_BYTES (4 * HID * LDT * 2 + 2 * HID * 4)
__global__ __launch_bounds__(512, 1)
void mlp_mma_kernel(const __half* __restrict__ W16,  // [2][HID*HID] this layer
                    const float* __restrict__ B1, const float* __restrict__ B2,
                    float* __restrict__ stats) {
    extern __shared__ __half smh[];
    __half* sW1 = smh;
    __half* sW2 = sW1 + HID * LDT;
    __half* sIn = sW2 + HID * LDT;
    __half* sT  = sIn + HID * LDT;
    float* sB1 = (float*)(sT + HID * LDT);
    float* sB2 = sB1 + HID;

    int tid = threadIdx.x;
    int lane = tid & 31;
    int wid = tid >> 5;
    int wr = wid >> 2;          // warp row block (0..3)
    int wc = wid & 3;           // warp col block (0..3)

    // load weights (padded) + biases
    for (int i = tid; i < HID * HID; i += 512) {
        int r = i >> 7, c = i & 127;
        sW1[r * LDT + c] = W16[i];
        sW2[r * LDT + c] = W16[HID * HID + i];
    }
    if (tid < HID) { sB1[tid] = B1[tid]; sB2[tid] = B2[tid]; }
    __syncthreads();

    int rpb = (N_NODES + gridDim.x - 1) / gridDim.x;
    int base = blockIdx.x * rpb;
    int rend = min(base + rpb, N_NODES);

    float ls[8], lss[8];
    #pragma unroll
    for (int j = 0; j < 8; j++) { ls[j] = 0.f; lss[j] = 0.f; }

    const int qlane = lane & 3;          // col pair selector
    const int rlane = lane >> 2;         // row within 8

    for (int rbase = base; rbase < rend; rbase += HID) {
        // load In tile (fp16 -> fp16, no conversion)
        for (int i = tid; i < HID * 16; i += 512) {
            int r = i >> 4, q = i & 15;
            int row = rbase + r;
            uint4 v = make_uint4(0u, 0u, 0u, 0u);
            if (row < rend) v = *reinterpret_cast<const uint4*>(g_zin16 + (size_t)row * HID + q * 8);
            *reinterpret_cast<uint4*>(&sIn[r * LDT + q * 8]) = v;
        }
        __syncthreads();

        // ---- stage 1: T = relu(In @ W1 + b1) ----
        float acc[2][4][4];
        #pragma unroll
        for (int mb = 0; mb < 2; mb++)
            #pragma unroll
            for (int nb = 0; nb < 4; nb++)
                #pragma unroll
                for (int j = 0; j < 4; j++) acc[mb][nb][j] = 0.f;

        #pragma unroll
        for (int ks = 0; ks < 8; ks++) {
            int k0 = ks * 16;
            unsigned a[2][4];
            #pragma unroll
            for (int mb = 0; mb < 2; mb++) {
                int row = wr * 32 + mb * 16 + (lane & 15);
                unsigned addr = smem_u32(&sIn[row * LDT + k0 + ((lane >> 4) << 3)]);
                ldsm_x4(addr, a[mb][0], a[mb][1], a[mb][2], a[mb][3]);
            }
            unsigned b[4][2];
            #pragma unroll
            for (int np = 0; np < 2; np++) {
                int krow = k0 + (lane & 15);
                int n0 = wc * 32 + np * 16 + ((lane >> 4) << 3);
                unsigned addr = smem_u32(&sW1[krow * LDT + n0]);
                unsigned r0, r1, r2, r3;
                ldsm_x4_t(addr, r0, r1, r2, r3);
                b[2 * np][0] = r0; b[2 * np][1] = r1;
                b[2 * np + 1][0] = r2; b[2 * np + 1][1] = r3;
            }
            #pragma unroll
            for (int mb = 0; mb < 2; mb++)
                #pragma unroll
                for (int nb = 0; nb < 4; nb++)
                    mma16816(acc[mb][nb][0], acc[mb][nb][1], acc[mb][nb][2], acc[mb][nb][3],
                             a[mb][0], a[mb][1], a[mb][2], a[mb][3], b[nb][0], b[nb][1]);
        }
        __syncthreads();   // done reading sIn (sT separate, but sync keeps tiles coherent)
        #pragma unroll
        for (int mb = 0; mb < 2; mb++) {
            #pragma unroll
            for (int nb = 0; nb < 4; nb++) {
                int col = wc * 32 + nb * 8 + 2 * qlane;
                float bx = sB1[col], by = sB1[col + 1];
                int rlo = wr * 32 + mb * 16 + rlane;
                *reinterpret_cast<__half2*>(&sT[rlo * LDT + col]) =
                    __floats2half2_rn(fmaxf(acc[mb][nb][0] + bx, 0.f),
                                      fmaxf(acc[mb][nb][1] + by, 0.f));
                *reinterpret_cast<__half2*>(&sT[(rlo + 8) * LDT + col]) =
                    __floats2half2_rn(fmaxf(acc[mb][nb][2] + bx, 0.f),
                                      fmaxf(acc[mb][nb][3] + by, 0.f));
            }
        }
        __syncthreads();

        // ---- stage 2: z = T @ W2 + b2 ----
        #pragma unroll
        for (int mb = 0; mb < 2; mb++)
            #pragma unroll
            for (int nb = 0; nb < 4; nb++)
                #pragma unroll
                for (int j = 0; j < 4; j++) acc[mb][nb][j] = 0.f;

        #pragma unroll
        for (int ks = 0; ks < 8; ks++) {
            int k0 = ks * 16;
            unsigned a[2][4];
            #pragma unroll
            for (int mb = 0; mb < 2; mb++) {
                int row = wr * 32 + mb * 16 + (lane & 15);
                unsigned addr = smem_u32(&sT[row * LDT + k0 + ((lane >> 4) << 3)]);
                ldsm_x4(addr, a[mb][0], a[mb][1], a[mb][2], a[mb][3]);
            }
            unsigned b[4][2];
            #pragma unroll
            for (int np = 0; np < 2; np++) {
                int krow = k0 + (lane & 15);
                int n0 = wc * 32 + np * 16 + ((lane >> 4) << 3);
                unsigned addr = smem_u32(&sW2[krow * LDT + n0]);
                unsigned r0, r1, r2, r3;
                ldsm_x4_t(addr, r0, r1, r2, r3);
                b[2 * np][0] = r0; b[2 * np][1] = r1;
                b[2 * np + 1][0] = r2; b[2 * np + 1][1] = r3;
            }
            #pragma unroll
            for (int mb = 0; mb < 2; mb++)
                #pragma unroll
                for (int nb = 0; nb < 4; nb++)
                    mma16816(acc[mb][nb][0], acc[mb][nb][1], acc[mb][nb][2], acc[mb][nb][3],
                             a[mb][0], a[mb][1], a[mb][2], a[mb][3], b[nb][0], b[nb][1]);
        }
        // epilogue: bias, store fp16, stats (guarded by row range)
        #pragma unroll
        for (int mb = 0; mb < 2; mb++) {
            #pragma unroll
            for (int nb = 0; nb < 4; nb++) {
                int col = wc * 32 + nb * 8 + 2 * qlane;
                float bx = sB2[col], by = sB2[col + 1];
                int rlo = rbase + wr * 32 + mb * 16 + rlane;
                float z0 = acc[mb][nb][0] + bx, z1 = acc[mb][nb][1] + by;
                float z2 = acc[mb][nb][2] + bx, z3 = acc[mb][nb][3] + by;
                if (rlo < rend) {
                    *reinterpret_cast<__half2*>(&g_z16[(size_t)rlo * HID + col]) =
                        __floats2half2_rn(z0, z1);
                    ls[2 * nb] += z0; lss[2 * nb] += z0 * z0;
                    ls[2 * nb + 1] += z1; lss[2 * nb + 1] += z1 * z1;
                }
                if (rlo + 8 < rend) {
                    *reinterpret_cast<__half2*>(&g_z16[(size_t)(rlo + 8) * HID + col]) =
                        __floats2half2_rn(z2, z3);
                    ls[2 * nb] += z2; lss[2 * nb] += z2 * z2;
                    ls[2 * nb + 1] += z3; lss[2 * nb + 1] += z3 * z3;
                }
            }
        }
        __syncthreads();
    }

    // stats: reduce over lanes sharing the same columns (lane>>2 varies)
    #pragma unroll
    for (int j = 0; j < 8; j++) {
        #pragma unroll
        for (int o = 4; o < 32; o <<= 1) {
            ls[j]  += __shfl_xor_sync(0xffffffffu, ls[j], o);
            lss[j] += __shfl_xor_sync(0xffffffffu, lss[j], o);
        }
    }
    if (lane < 4) {
        #pragma unroll
        for (int nb = 0; nb < 4; nb++) {
            #pragma unroll
            for (int j = 0; j < 2; j++) {
                int col = wc * 32 + nb * 8 + 2 * lane + j;
                atomicAdd(&stats[col], ls[2 * nb + j]);
                atomicAdd(&stats[HID + col], lss[2 * nb + j]);
            }
        }
    }
}

// ---------------- last layer: BN + relu + pool (reads z16) ------------------
__global__ void bn_pool_kernel(const float* __restrict__ gamma,
                               const float* __restrict__ beta,
                               const float* __restrict__ stats,
                               const int* __restrict__ batch) {
    int i = blockIdx.x * blockDim.x + threadIdx.x;
    const int n4 = N_NODES * HID / 4;
    if (i >= n4) return;
    int n = i >> 5;
    int c0 = (i & 31) * 4;
    float4 z = h16_load4(g_z16 + (size_t)i * 4);
    float za[4] = {z.x, z.y, z.z, z.w};
    float out[4];
    const float invN = 1.0f / (float)N_NODES;
    #pragma unroll
    for (int j = 0; j < 4; j++) {
        int c = c0 + j;
        float mean = stats[c] * invN;
        float var = stats[HID + c] * invN - mean * mean;
        float rstd = rsqrtf(var + BN_EPS);
        float o = gamma[c] * (za[j] - mean) * rstd + beta[c];
        out[j] = fmaxf(o, 0.f);
    }
    int gi = __ldg(&batch[n]);
    red_add_v4(g_pool + (size_t)gi * HID + c0,
               make_float4(out[0], out[1], out[2], out[3]));
}

// ---------------- head: out = relu(g@W1+b1)@W2+b2 ---------------------------
__global__ void head_kernel(const float* __restrict__ w1, const float* __restrict__ b1,
                            const float* __restrict__ w2, const float* __restrict__ b2,
                            float* __restrict__ out) {
    __shared__ float srow[HID];
    __shared__ float st[HID];
    int gi = blockIdx.x;
    int c = threadIdx.x;
    srow[c] = g_pool[(size_t)gi * HID + c];
    __syncthreads();
    float acc = b1[c];
    for (int k = 0; k < HID; k++) acc += srow[k] * w1[k * HID + c];
    st[c] = fmaxf(acc, 0.f);
    __syncthreads();
    if (c < 2) {
        float o = b2[c];
        for (int k = 0; k < HID; k++) o += st[k] * w2[k * 2 + c];
        out[gi * 2 + c] = o;
    }
}

// ---------------- launch -----------------------------------------------------
extern "C" void kernel_launch(void* const* d_in, const int* in_sizes, int n_in,
                              void* d_out, int out_size) {
    const float* x        = (const float*)d_in[0];
    const int*   eidx     = (const int*)d_in[1];
    const float* eattr    = (const float*)d_in[2];
    const int*   batch    = (const int*)d_in[3];
    const float* node_w   = (const float*)d_in[4];
    const float* node_b   = (const float*)d_in[5];
    const float* edge_w   = (const float*)d_in[6];
    const float* edge_b   = (const float*)d_in[7];
    const float* mlp_w1   = (const float*)d_in[8];
    const float* mlp_b1   = (const float*)d_in[9];
    const float* mlp_w2   = (const float*)d_in[10];
    const float* mlp_b2   = (const float*)d_in[11];
    const float* bn_gamma = (const float*)d_in[12];
    const float* bn_beta  = (const float*)d_in[13];
    const float* head_w1  = (const float*)d_in[14];
    const float* head_b1  = (const float*)d_in[15];
    const float* head_w2  = (const float*)d_in[16];
    const float* head_b2  = (const float*)d_in[17];
    float* out = (float*)d_out;

    cudaFuncSetAttribute(mlp_mma_kernel, cudaFuncAttributeMaxDynamicSharedMemorySize,
                         MLP_SMEM_BYTES);

    float* d_stats;
    cudaGetSymbolAddress((void**)&d_stats, g_stats);
    __half* d_w16;
    cudaGetSymbolAddress((void**)&d_w16, g_w16);

    // weight conversion (fp32 -> fp16), one pass
    convert_w_kernel<<<(2 * NLAYERS * HID * HID + 255) / 256, 256>>>(mlp_w1, mlp_w2);

    // encoder (also zeros cnt/pool/stats) -> z16
    encoder_kernel<<<512, 256>>>(x, node_w, node_b);

    // CSR build (parallel scan), then fused fill + edge encoder
    csr_count_kernel<<<(N_EDGES + 255) / 256, 256>>>(eidx);
    chunk_sum_kernel<<<NCHUNK / 128, 128>>>();
    chunk_scan_kernel<<<1, NCHUNK>>>();
    chunk_offs_kernel<<<NCHUNK / 128, 128>>>();
    edge_enc_fill_kernel<<<2048, 256>>>(eattr, eidx, edge_w, edge_b);

    for (int l = 0; l < NLAYERS; l++) {
        if (l == 0) {
            agg_kernel<false><<<2048, 256>>>(nullptr, nullptr, nullptr);
        } else {
            agg_kernel<true><<<2048, 256>>>(bn_gamma + (size_t)(l - 1) * HID,
                                            bn_beta + (size_t)(l - 1) * HID,
                                            d_stats + (size_t)(l - 1) * 2 * HID);
        }
        mlp_mma_kernel<<<148, 512, MLP_SMEM_BYTES>>>(
            d_w16 + (size_t)l * 2 * HID * HID,
            mlp_b1 + (size_t)l * HID,
            mlp_b2 + (size_t)l * HID,
            d_stats + (size_t)l * 2 * HID);
    }

    bn_pool_kernel<<<(N_NODES * HID / 4 + 255) / 256, 256>>>(
        bn_gamma + (size_t)(NLAYERS - 1) * HID,
        bn_beta + (size_t)(NLAYERS - 1) * HID,
        d_stats + (size_t)(NLAYERS - 1) * 2 * HID, batch);
    head_kernel<<<NGRAPHS, HID>>>(head_w1, head_b1, head_w2, head_b2, out);
}